// round 3
// baseline (speedup 1.0000x reference)
#include <cuda_runtime.h>
#include <cuda_pipeline.h>
#include <math.h>

// Problem dims
#define Bz 64
#define Tz 128
#define Sz 100
#define Az 16
#define Hz 120
#define G4 480      // 4*H
#define KTOT 136    // A + H
// LSTM kernel config
#define NROW 50     // rows per block (6400 = 128 * 50)
#define NBLK 128
#define NTH 256
#define TM 5
#define TQ 6        // packed as 3 f32x2 pairs
#define NACT 200    // 10 rowgrps * 20 qgrps
#define ROWPAD 51
#define KTILE 17
#define NTILE 8     // 8 * 17 = 136
// MLP1 config
#define KCH 79
#define NCHUNK 128  // 128 * 79 = 10112 >= 10000

#define SMEM_BYTES ((KTOT * ROWPAD + 2 * KTILE * G4 + G4) * 4)

typedef unsigned long long ull;

// ---------------- packed f32x2 helpers ----------------
__device__ __forceinline__ ull dup2(float v) {
    ull r; asm("mov.b64 %0, {%1, %1};" : "=l"(r) : "f"(v)); return r;
}
__device__ __forceinline__ void unpack2(ull p, float& lo, float& hi) {
    asm("mov.b64 {%0, %1}, %2;" : "=f"(lo), "=f"(hi) : "l"(p));
}
__device__ __forceinline__ void ffma2(ull& d, ull a, ull b) {
    asm("fma.rn.f32x2 %0, %1, %2, %0;" : "+l"(d) : "l"(a), "l"(b));
}

// ---------------- scratch (static device arrays, allowed) ----------------
__device__ float g_Wc[KTOT * G4];          // combined transposed weights [k][j]
__device__ float g_bias[G4];               // b_ih + b_hh
__device__ float g_W2t[10000 * 256];       // W2 transposed [k][o]
__device__ float g_s[Bz * Sz];             // scores
__device__ float g_foo[Bz * Sz * Sz];      // p_hat flattened
__device__ float g_part[NCHUNK * Bz * 256];// MLP1 partials
__device__ float g_z1[Bz * 256];           // relu(MLP1)

__device__ __forceinline__ float sigm(float x) {
    return __fdividef(1.f, 1.f + __expf(-x));
}
__device__ __forceinline__ float tanh_fast(float x) {
    return __fdividef(2.f, 1.f + __expf(-2.f * x)) - 1.f;
}

// ---------------- prep: weight transpose / combine ----------------
__global__ void prep_kernel(const float* __restrict__ Wih,
                            const float* __restrict__ Whh,
                            const float* __restrict__ bih,
                            const float* __restrict__ bhh,
                            const float* __restrict__ W2) {
    int idx = blockIdx.x * blockDim.x + threadIdx.x;
    int stride = gridDim.x * blockDim.x;
    for (int i = idx; i < KTOT * G4; i += stride) {
        int k = i / G4, j = i - k * G4;
        g_Wc[i] = (k < Az) ? Wih[j * Az + k] : Whh[j * Hz + (k - Az)];
    }
    for (int i = idx; i < G4; i += stride) g_bias[i] = bih[i] + bhh[i];
    for (int i = idx; i < 10000 * 256; i += stride) {
        int k = i >> 8, o = i & 255;
        g_W2t[i] = W2[o * 10000 + k];
    }
}

// ---------------- LSTM: persistent per-row-group, 128 steps, f32x2 GEMM ----------------
__global__ void __launch_bounds__(NTH, 1)
lstm_kernel(const float* __restrict__ x,
            const float* __restrict__ w_lin,
            const float* __restrict__ b_lin) {
    extern __shared__ float smf[];
    float* hx = smf;                          // [KTOT][ROWPAD]: k<16 = x_t, else h
    float* wt = smf + KTOT * ROWPAD;          // [2][KTILE*G4] W double buffer
    float* bias_sm = wt + 2 * KTILE * G4;     // [G4]

    const int tid = threadIdx.x;
    const int r0 = blockIdx.x * NROW;

    for (int i = tid; i < G4; i += NTH) bias_sm[i] = g_bias[i];
    for (int i = tid; i < Hz * ROWPAD; i += NTH) hx[Az * ROWPAD + i] = 0.f;

    // x(t=0) transposed into hx[0..15][row]
    for (int i = tid; i < NROW * 4; i += NTH) {
        int m = i >> 2, p = i & 3;
        int r = r0 + m;
        int b = r / Sz, s = r - b * Sz;
        float4 v = *reinterpret_cast<const float4*>(
            x + (((size_t)b * Tz + 0) * Sz + s) * Az + p * 4);
        hx[(p * 4 + 0) * ROWPAD + m] = v.x;
        hx[(p * 4 + 1) * ROWPAD + m] = v.y;
        hx[(p * 4 + 2) * ROWPAD + m] = v.z;
        hx[(p * 4 + 3) * ROWPAD + m] = v.w;
    }

    const bool act = tid < NACT;
    const int rowgrp = tid / 20;         // 0..9
    const int qgrp = tid - rowgrp * 20;  // 0..19
    const int m0 = rowgrp * TM;
    const int q0 = qgrp * TQ;            // even -> 8B-aligned pair loads

    float c[TM][TQ];
    #pragma unroll
    for (int i = 0; i < TM; i++)
        #pragma unroll
        for (int u = 0; u < TQ; u++) c[i][u] = 0.f;

    __syncthreads();

    for (int t = 0; t < Tz; ++t) {
        // acc[i][up][g] : packed pair of gate outputs (q0+2up, q0+2up+1)
        ull acc[TM][TQ / 2][4];
        if (act) {
            #pragma unroll
            for (int g = 0; g < 4; g++)
                #pragma unroll
                for (int up = 0; up < TQ / 2; up++) {
                    ull bv = *reinterpret_cast<const ull*>(
                        bias_sm + g * Hz + q0 + 2 * up);
                    #pragma unroll
                    for (int i = 0; i < TM; i++) acc[i][up][g] = bv;
                }
        }

        // prefetch W tile 0
        {
            const float* src = g_Wc;
            float* dst = wt;
            for (int i = tid; i < (KTILE * G4) / 4; i += NTH)
                __pipeline_memcpy_async(dst + i * 4, src + i * 4, 16);
            __pipeline_commit();
        }

        for (int tt = 0; tt < NTILE; ++tt) {
            __pipeline_wait_prior(0);
            __syncthreads();  // tile tt resident + everyone done with other buffer
            if (tt + 1 < NTILE) {
                const float* src = g_Wc + (tt + 1) * (KTILE * G4);
                float* dst = wt + ((tt + 1) & 1) * (KTILE * G4);
                for (int i = tid; i < (KTILE * G4) / 4; i += NTH)
                    __pipeline_memcpy_async(dst + i * 4, src + i * 4, 16);
                __pipeline_commit();
            }
            if (act) {
                const float* wb = wt + (tt & 1) * (KTILE * G4);
                const int kb = tt * KTILE;
                #pragma unroll 1
                for (int k = 0; k < KTILE; ++k) {
                    ull a2[TM];
                    const float* hrow = hx + (kb + k) * ROWPAD + m0;
                    #pragma unroll
                    for (int i = 0; i < TM; i++) a2[i] = dup2(hrow[i]);
                    const float* wk = wb + k * G4 + q0;
                    #pragma unroll
                    for (int g = 0; g < 4; g++) {
                        #pragma unroll
                        for (int up = 0; up < TQ / 2; up++) {
                            ull w2 = *reinterpret_cast<const ull*>(
                                wk + g * Hz + 2 * up);
                            #pragma unroll
                            for (int i = 0; i < TM; i++)
                                ffma2(acc[i][up][g], a2[i], w2);
                        }
                    }
                }
            }
        }

        float hreg[TM][TQ];
        if (act) {
            #pragma unroll
            for (int i = 0; i < TM; i++)
                #pragma unroll
                for (int up = 0; up < TQ / 2; up++) {
                    float iv[2], fv[2], gv[2], ov[2];
                    unpack2(acc[i][up][0], iv[0], iv[1]);
                    unpack2(acc[i][up][1], fv[0], fv[1]);
                    unpack2(acc[i][up][2], gv[0], gv[1]);
                    unpack2(acc[i][up][3], ov[0], ov[1]);
                    #pragma unroll
                    for (int e = 0; e < 2; e++) {
                        int u = 2 * up + e;
                        float ig = sigm(iv[e]);
                        float fg = sigm(fv[e]);
                        float gg = tanh_fast(gv[e]);
                        float og = sigm(ov[e]);
                        float cc = fmaf(fg, c[i][u], ig * gg);
                        c[i][u] = cc;
                        hreg[i][u] = og * tanh_fast(cc);
                    }
                }
        }
        __syncthreads();  // all GEMM reads of hx complete before overwrite
        if (act) {
            #pragma unroll
            for (int u = 0; u < TQ; u++)
                #pragma unroll
                for (int i = 0; i < TM; i++)
                    hx[(Az + q0 + u) * ROWPAD + m0 + i] = hreg[i][u];
        }
        if (t + 1 < Tz) {
            for (int i = tid; i < NROW * 4; i += NTH) {
                int m = i >> 2, p = i & 3;
                int r = r0 + m;
                int b = r / Sz, s = r - b * Sz;
                float4 v = *reinterpret_cast<const float4*>(
                    x + (((size_t)b * Tz + (t + 1)) * Sz + s) * Az + p * 4);
                hx[(p * 4 + 0) * ROWPAD + m] = v.x;
                hx[(p * 4 + 1) * ROWPAD + m] = v.y;
                hx[(p * 4 + 2) * ROWPAD + m] = v.z;
                hx[(p * 4 + 3) * ROWPAD + m] = v.w;
            }
        }
        // next-iteration tt=0 wait+sync orders these writes vs. next GEMM reads
    }

    __syncthreads();
    // score head: s = h_last . w_lin + b_lin   (h_last lives in hx)
    if (tid < NROW) {
        float sv = b_lin[0];
        #pragma unroll 4
        for (int q = 0; q < Hz; q++)
            sv = fmaf(w_lin[q], hx[(Az + q) * ROWPAD + tid], sv);
        g_s[r0 + tid] = sv;
    }
}

// ---------------- NeuralSort relaxed permutation + softmax ----------------
__global__ void sort_kernel() {
    __shared__ float s_sm[Sz];
    __shared__ float rs_sm[Sz];
    int b = blockIdx.x, tid = threadIdx.x;
    if (tid < Sz) s_sm[tid] = g_s[b * Sz + tid];
    __syncthreads();
    if (tid < Sz) {
        float si = s_sm[tid], sum = 0.f;
        for (int j = 0; j < Sz; j++) sum += fabsf(si - s_sm[j]);
        rs_sm[tid] = sum;
    }
    __syncthreads();
    int warp = tid >> 5, lane = tid & 31;
    for (int i = warp; i < Sz; i += 4) {
        float scal = (float)(Sz - 1 - 2 * i);  // 99 - 2i
        float v[4], e[4];
        float mx = -INFINITY;
        #pragma unroll
        for (int cc = 0; cc < 4; cc++) {
            int j = lane + 32 * cc;
            v[cc] = (j < Sz) ? (s_sm[j] * scal - rs_sm[j]) * 0.2f : -INFINITY;
            mx = fmaxf(mx, v[cc]);
        }
        #pragma unroll
        for (int o = 16; o; o >>= 1) mx = fmaxf(mx, __shfl_xor_sync(0xffffffffu, mx, o));
        float sum = 0.f;
        #pragma unroll
        for (int cc = 0; cc < 4; cc++) {
            int j = lane + 32 * cc;
            e[cc] = (j < Sz) ? __expf(v[cc] - mx) : 0.f;
            sum += e[cc];
        }
        #pragma unroll
        for (int o = 16; o; o >>= 1) sum += __shfl_xor_sync(0xffffffffu, sum, o);
        float inv = __fdividef(1.f, sum);
        #pragma unroll
        for (int cc = 0; cc < 4; cc++) {
            int j = lane + 32 * cc;
            if (j < Sz) g_foo[(size_t)b * (Sz * Sz) + i * Sz + j] = e[cc] * inv;
        }
    }
}

// ---------------- MLP1 partial GEMM: K-split over 128 chunks, f32x2 ----------------
__global__ void __launch_bounds__(256) mlp1_kernel() {
    int c = blockIdx.x, tid = threadIdx.x;
    int k0 = c * KCH;
    int kend = min(k0 + KCH, 10000);
    int bg = tid >> 5;   // 8 row groups (of 8 batches)
    int og = tid & 31;   // 32 col groups (of 8 outputs)
    ull acc[8][4];
    #pragma unroll
    for (int i = 0; i < 8; i++)
        #pragma unroll
        for (int j = 0; j < 4; j++) acc[i][j] = 0;
    const float* fooB = g_foo + (size_t)(bg * 8) * 10000;
    for (int k = k0; k < kend; ++k) {
        ull a2[8];
        #pragma unroll
        for (int i = 0; i < 8; i++) a2[i] = dup2(fooB[(size_t)i * 10000 + k]);
        const ull* wrow = reinterpret_cast<const ull*>(g_W2t + (size_t)k * 256 + og * 8);
        #pragma unroll
        for (int j = 0; j < 4; j++) {
            ull w2 = wrow[j];
            #pragma unroll
            for (int i = 0; i < 8; i++) ffma2(acc[i][j], a2[i], w2);
        }
    }
    #pragma unroll
    for (int i = 0; i < 8; i++)
        #pragma unroll
        for (int j = 0; j < 4; j++) {
            float lo, hi;
            unpack2(acc[i][j], lo, hi);
            size_t base = ((size_t)c * 64 + bg * 8 + i) * 256 + og * 8 + 2 * j;
            g_part[base] = lo;
            g_part[base + 1] = hi;
        }
}

// ---------------- reduce partials + bias + relu ----------------
__global__ void reduce_kernel(const float* __restrict__ b2) {
    int b = blockIdx.x, o = threadIdx.x;
    float s = b2[o];
    for (int c = 0; c < NCHUNK; ++c) s += g_part[((size_t)c * 64 + b) * 256 + o];
    g_z1[b * 256 + o] = fmaxf(s, 0.f);
}

// ---------------- MLP2 + final softmax ----------------
__global__ void mlp2_kernel(const float* __restrict__ W3,
                            const float* __restrict__ b3,
                            float* __restrict__ out) {
    __shared__ float z1s[256];
    __shared__ float zs[Sz];
    __shared__ float s_mx, s_sum;
    int b = blockIdx.x, tid = threadIdx.x;  // 128 threads
    z1s[tid] = g_z1[b * 256 + tid];
    z1s[tid + 128] = g_z1[b * 256 + tid + 128];
    __syncthreads();
    if (tid < Sz) {
        float accv = b3[tid];
        const float* wr = W3 + tid * 256;
        #pragma unroll 4
        for (int k = 0; k < 256; k++) accv = fmaf(z1s[k], wr[k], accv);
        zs[tid] = accv;
    }
    __syncthreads();
    if (tid == 0) {
        float mx = -INFINITY;
        for (int j = 0; j < Sz; j++) mx = fmaxf(mx, zs[j]);
        float sum = 0.f;
        for (int j = 0; j < Sz; j++) sum += __expf(zs[j] - mx);
        s_mx = mx;
        s_sum = sum;
    }
    __syncthreads();
    if (tid < Sz)
        out[b * Sz + tid] = __expf(zs[tid] - s_mx) * __fdividef(1.f, s_sum);
}

// ---------------- launch ----------------
extern "C" void kernel_launch(void* const* d_in, const int* in_sizes, int n_in,
                              void* d_out, int out_size) {
    const float* x    = (const float*)d_in[0];
    const float* Wih  = (const float*)d_in[1];
    const float* Whh  = (const float*)d_in[2];
    const float* bih  = (const float*)d_in[3];
    const float* bhh  = (const float*)d_in[4];
    const float* wlin = (const float*)d_in[5];
    const float* blin = (const float*)d_in[6];
    const float* W2   = (const float*)d_in[7];
    const float* b2   = (const float*)d_in[8];
    const float* W3   = (const float*)d_in[9];
    const float* b3   = (const float*)d_in[10];
    float* out = (float*)d_out;
    (void)in_sizes; (void)n_in; (void)out_size;

    cudaFuncSetAttribute(lstm_kernel,
                         cudaFuncAttributeMaxDynamicSharedMemorySize, SMEM_BYTES);

    prep_kernel<<<512, 256>>>(Wih, Whh, bih, bhh, W2);
    lstm_kernel<<<NBLK, NTH, SMEM_BYTES>>>(x, wlin, blin);
    sort_kernel<<<Bz, 128>>>();
    mlp1_kernel<<<NCHUNK, 256>>>();
    reduce_kernel<<<Bz, 256>>>(b2);
    mlp2_kernel<<<Bz, 128>>>(W3, b3, out);
}

// round 4
// speedup vs baseline: 1.0002x; 1.0002x over previous
#include <cuda_runtime.h>
#include <cuda_pipeline.h>
#include <math.h>

// Problem dims
#define Bz 64
#define Tz 128
#define Sz 100
#define Az 16
#define Hz 120
#define G4 480      // 4*H
#define KTOT 136    // A + H
// LSTM kernel config
#define NROW 50     // rows per block (6400 = 128 * 50)
#define NBLK 128
#define NTH 256
#define TM 5
#define TQ 6        // packed as 3 f32x2 pairs
#define NACT 200    // 10 rowgrps * 20 qgrps
#define ROWPAD 51
#define KTILE 17
#define NTILE 8     // 8 * 17 = 136
// MLP1 config
#define KCH 79
#define NCHUNK 128  // 128 * 79 = 10112 >= 10000

#define SMEM_BYTES ((KTOT * ROWPAD + 2 * KTILE * G4 + G4) * 4)

typedef unsigned long long ull;

// ---------------- packed f32x2 helpers ----------------
__device__ __forceinline__ ull dup2(float v) {
    ull r; asm("mov.b64 %0, {%1, %1};" : "=l"(r) : "f"(v)); return r;
}
__device__ __forceinline__ void unpack2(ull p, float& lo, float& hi) {
    asm("mov.b64 {%0, %1}, %2;" : "=f"(lo), "=f"(hi) : "l"(p));
}
__device__ __forceinline__ void ffma2(ull& d, ull a, ull b) {
    asm("fma.rn.f32x2 %0, %1, %2, %0;" : "+l"(d) : "l"(a), "l"(b));
}

// ---------------- scratch (static device arrays, allowed) ----------------
__device__ float g_Wc[KTOT * G4];          // combined transposed weights [k][j]
__device__ float g_bias[G4];               // b_ih + b_hh
__device__ float g_W2t[10000 * 256];       // W2 transposed [k][o]
__device__ float g_s[Bz * Sz];             // scores
__device__ float g_foo[Bz * Sz * Sz];      // p_hat flattened
__device__ float g_part[NCHUNK * Bz * 256];// MLP1 partials
__device__ float g_z1[Bz * 256];           // relu(MLP1)

__device__ __forceinline__ float sigm(float x) {
    return __fdividef(1.f, 1.f + __expf(-x));
}
__device__ __forceinline__ float tanh_fast(float x) {
    return __fdividef(2.f, 1.f + __expf(-2.f * x)) - 1.f;
}

// ---------------- prep: weight transpose / combine ----------------
__global__ void prep_kernel(const float* __restrict__ Wih,
                            const float* __restrict__ Whh,
                            const float* __restrict__ bih,
                            const float* __restrict__ bhh,
                            const float* __restrict__ W2) {
    int idx = blockIdx.x * blockDim.x + threadIdx.x;
    int stride = gridDim.x * blockDim.x;
    for (int i = idx; i < KTOT * G4; i += stride) {
        int k = i / G4, j = i - k * G4;
        g_Wc[i] = (k < Az) ? Wih[j * Az + k] : Whh[j * Hz + (k - Az)];
    }
    for (int i = idx; i < G4; i += stride) g_bias[i] = bih[i] + bhh[i];
    for (int i = idx; i < 10000 * 256; i += stride) {
        int k = i >> 8, o = i & 255;
        g_W2t[i] = W2[o * 10000 + k];
    }
}

// ---------------- LSTM: persistent per-row-group, 128 steps, f32x2 GEMM ----------------
__global__ void __launch_bounds__(NTH, 1)
lstm_kernel(const float* __restrict__ x,
            const float* __restrict__ w_lin,
            const float* __restrict__ b_lin) {
    extern __shared__ float smf[];
    float* hx = smf;                          // [KTOT][ROWPAD]: k<16 = x_t, else h
    float* wt = smf + KTOT * ROWPAD;          // [2][KTILE*G4] W double buffer
    float* bias_sm = wt + 2 * KTILE * G4;     // [G4]

    const int tid = threadIdx.x;
    const int r0 = blockIdx.x * NROW;

    for (int i = tid; i < G4; i += NTH) bias_sm[i] = g_bias[i];
    for (int i = tid; i < Hz * ROWPAD; i += NTH) hx[Az * ROWPAD + i] = 0.f;

    // x(t=0) transposed into hx[0..15][row]
    for (int i = tid; i < NROW * 4; i += NTH) {
        int m = i >> 2, p = i & 3;
        int r = r0 + m;
        int b = r / Sz, s = r - b * Sz;
        float4 v = *reinterpret_cast<const float4*>(
            x + (((size_t)b * Tz + 0) * Sz + s) * Az + p * 4);
        hx[(p * 4 + 0) * ROWPAD + m] = v.x;
        hx[(p * 4 + 1) * ROWPAD + m] = v.y;
        hx[(p * 4 + 2) * ROWPAD + m] = v.z;
        hx[(p * 4 + 3) * ROWPAD + m] = v.w;
    }

    const bool act = tid < NACT;
    const int rowgrp = tid / 20;         // 0..9
    const int qgrp = tid - rowgrp * 20;  // 0..19
    const int m0 = rowgrp * TM;
    const int q0 = qgrp * TQ;            // even -> 8B-aligned pair loads

    float c[TM][TQ];
    #pragma unroll
    for (int i = 0; i < TM; i++)
        #pragma unroll
        for (int u = 0; u < TQ; u++) c[i][u] = 0.f;

    __syncthreads();

    for (int t = 0; t < Tz; ++t) {
        // acc[i][up][g] : packed pair of gate outputs (q0+2up, q0+2up+1)
        ull acc[TM][TQ / 2][4];
        if (act) {
            #pragma unroll
            for (int g = 0; g < 4; g++)
                #pragma unroll
                for (int up = 0; up < TQ / 2; up++) {
                    ull bv = *reinterpret_cast<const ull*>(
                        bias_sm + g * Hz + q0 + 2 * up);
                    #pragma unroll
                    for (int i = 0; i < TM; i++) acc[i][up][g] = bv;
                }
        }

        // prefetch W tile 0
        {
            const float* src = g_Wc;
            float* dst = wt;
            for (int i = tid; i < (KTILE * G4) / 4; i += NTH)
                __pipeline_memcpy_async(dst + i * 4, src + i * 4, 16);
            __pipeline_commit();
        }

        for (int tt = 0; tt < NTILE; ++tt) {
            __pipeline_wait_prior(0);
            __syncthreads();  // tile tt resident + everyone done with other buffer
            if (tt + 1 < NTILE) {
                const float* src = g_Wc + (tt + 1) * (KTILE * G4);
                float* dst = wt + ((tt + 1) & 1) * (KTILE * G4);
                for (int i = tid; i < (KTILE * G4) / 4; i += NTH)
                    __pipeline_memcpy_async(dst + i * 4, src + i * 4, 16);
                __pipeline_commit();
            }
            if (act) {
                const float* wb = wt + (tt & 1) * (KTILE * G4);
                const int kb = tt * KTILE;
                #pragma unroll 1
                for (int k = 0; k < KTILE; ++k) {
                    ull a2[TM];
                    const float* hrow = hx + (kb + k) * ROWPAD + m0;
                    #pragma unroll
                    for (int i = 0; i < TM; i++) a2[i] = dup2(hrow[i]);
                    const float* wk = wb + k * G4 + q0;
                    #pragma unroll
                    for (int g = 0; g < 4; g++) {
                        #pragma unroll
                        for (int up = 0; up < TQ / 2; up++) {
                            ull w2 = *reinterpret_cast<const ull*>(
                                wk + g * Hz + 2 * up);
                            #pragma unroll
                            for (int i = 0; i < TM; i++)
                                ffma2(acc[i][up][g], a2[i], w2);
                        }
                    }
                }
            }
        }

        float hreg[TM][TQ];
        if (act) {
            #pragma unroll
            for (int i = 0; i < TM; i++)
                #pragma unroll
                for (int up = 0; up < TQ / 2; up++) {
                    float iv[2], fv[2], gv[2], ov[2];
                    unpack2(acc[i][up][0], iv[0], iv[1]);
                    unpack2(acc[i][up][1], fv[0], fv[1]);
                    unpack2(acc[i][up][2], gv[0], gv[1]);
                    unpack2(acc[i][up][3], ov[0], ov[1]);
                    #pragma unroll
                    for (int e = 0; e < 2; e++) {
                        int u = 2 * up + e;
                        float ig = sigm(iv[e]);
                        float fg = sigm(fv[e]);
                        float gg = tanh_fast(gv[e]);
                        float og = sigm(ov[e]);
                        float cc = fmaf(fg, c[i][u], ig * gg);
                        c[i][u] = cc;
                        hreg[i][u] = og * tanh_fast(cc);
                    }
                }
        }
        __syncthreads();  // all GEMM reads of hx complete before overwrite
        if (act) {
            #pragma unroll
            for (int u = 0; u < TQ; u++)
                #pragma unroll
                for (int i = 0; i < TM; i++)
                    hx[(Az + q0 + u) * ROWPAD + m0 + i] = hreg[i][u];
        }
        if (t + 1 < Tz) {
            for (int i = tid; i < NROW * 4; i += NTH) {
                int m = i >> 2, p = i & 3;
                int r = r0 + m;
                int b = r / Sz, s = r - b * Sz;
                float4 v = *reinterpret_cast<const float4*>(
                    x + (((size_t)b * Tz + (t + 1)) * Sz + s) * Az + p * 4);
                hx[(p * 4 + 0) * ROWPAD + m] = v.x;
                hx[(p * 4 + 1) * ROWPAD + m] = v.y;
                hx[(p * 4 + 2) * ROWPAD + m] = v.z;
                hx[(p * 4 + 3) * ROWPAD + m] = v.w;
            }
        }
        // next-iteration tt=0 wait+sync orders these writes vs. next GEMM reads
    }

    __syncthreads();
    // score head: s = h_last . w_lin + b_lin   (h_last lives in hx)
    if (tid < NROW) {
        float sv = b_lin[0];
        #pragma unroll 4
        for (int q = 0; q < Hz; q++)
            sv = fmaf(w_lin[q], hx[(Az + q) * ROWPAD + tid], sv);
        g_s[r0 + tid] = sv;
    }
}

// ---------------- NeuralSort relaxed permutation + softmax ----------------
__global__ void sort_kernel() {
    __shared__ float s_sm[Sz];
    __shared__ float rs_sm[Sz];
    int b = blockIdx.x, tid = threadIdx.x;
    if (tid < Sz) s_sm[tid] = g_s[b * Sz + tid];
    __syncthreads();
    if (tid < Sz) {
        float si = s_sm[tid], sum = 0.f;
        for (int j = 0; j < Sz; j++) sum += fabsf(si - s_sm[j]);
        rs_sm[tid] = sum;
    }
    __syncthreads();
    int warp = tid >> 5, lane = tid & 31;
    for (int i = warp; i < Sz; i += 4) {
        float scal = (float)(Sz - 1 - 2 * i);  // 99 - 2i
        float v[4], e[4];
        float mx = -INFINITY;
        #pragma unroll
        for (int cc = 0; cc < 4; cc++) {
            int j = lane + 32 * cc;
            v[cc] = (j < Sz) ? (s_sm[j] * scal - rs_sm[j]) * 0.2f : -INFINITY;
            mx = fmaxf(mx, v[cc]);
        }
        #pragma unroll
        for (int o = 16; o; o >>= 1) mx = fmaxf(mx, __shfl_xor_sync(0xffffffffu, mx, o));
        float sum = 0.f;
        #pragma unroll
        for (int cc = 0; cc < 4; cc++) {
            int j = lane + 32 * cc;
            e[cc] = (j < Sz) ? __expf(v[cc] - mx) : 0.f;
            sum += e[cc];
        }
        #pragma unroll
        for (int o = 16; o; o >>= 1) sum += __shfl_xor_sync(0xffffffffu, sum, o);
        float inv = __fdividef(1.f, sum);
        #pragma unroll
        for (int cc = 0; cc < 4; cc++) {
            int j = lane + 32 * cc;
            if (j < Sz) g_foo[(size_t)b * (Sz * Sz) + i * Sz + j] = e[cc] * inv;
        }
    }
}

// ---------------- MLP1 partial GEMM: K-split over 128 chunks, f32x2 ----------------
__global__ void __launch_bounds__(256) mlp1_kernel() {
    int c = blockIdx.x, tid = threadIdx.x;
    int k0 = c * KCH;
    int kend = min(k0 + KCH, 10000);
    int bg = tid >> 5;   // 8 row groups (of 8 batches)
    int og = tid & 31;   // 32 col groups (of 8 outputs)
    ull acc[8][4];
    #pragma unroll
    for (int i = 0; i < 8; i++)
        #pragma unroll
        for (int j = 0; j < 4; j++) acc[i][j] = 0;
    const float* fooB = g_foo + (size_t)(bg * 8) * 10000;
    for (int k = k0; k < kend; ++k) {
        ull a2[8];
        #pragma unroll
        for (int i = 0; i < 8; i++) a2[i] = dup2(fooB[(size_t)i * 10000 + k]);
        const ull* wrow = reinterpret_cast<const ull*>(g_W2t + (size_t)k * 256 + og * 8);
        #pragma unroll
        for (int j = 0; j < 4; j++) {
            ull w2 = wrow[j];
            #pragma unroll
            for (int i = 0; i < 8; i++) ffma2(acc[i][j], a2[i], w2);
        }
    }
    #pragma unroll
    for (int i = 0; i < 8; i++)
        #pragma unroll
        for (int j = 0; j < 4; j++) {
            float lo, hi;
            unpack2(acc[i][j], lo, hi);
            size_t base = ((size_t)c * 64 + bg * 8 + i) * 256 + og * 8 + 2 * j;
            g_part[base] = lo;
            g_part[base + 1] = hi;
        }
}

// ---------------- reduce partials + bias + relu ----------------
__global__ void reduce_kernel(const float* __restrict__ b2) {
    int b = blockIdx.x, o = threadIdx.x;
    float s = b2[o];
    for (int c = 0; c < NCHUNK; ++c) s += g_part[((size_t)c * 64 + b) * 256 + o];
    g_z1[b * 256 + o] = fmaxf(s, 0.f);
}

// ---------------- MLP2 + final softmax ----------------
__global__ void mlp2_kernel(const float* __restrict__ W3,
                            const float* __restrict__ b3,
                            float* __restrict__ out) {
    __shared__ float z1s[256];
    __shared__ float zs[Sz];
    __shared__ float s_mx, s_sum;
    int b = blockIdx.x, tid = threadIdx.x;  // 128 threads
    z1s[tid] = g_z1[b * 256 + tid];
    z1s[tid + 128] = g_z1[b * 256 + tid + 128];
    __syncthreads();
    if (tid < Sz) {
        float accv = b3[tid];
        const float* wr = W3 + tid * 256;
        #pragma unroll 4
        for (int k = 0; k < 256; k++) accv = fmaf(z1s[k], wr[k], accv);
        zs[tid] = accv;
    }
    __syncthreads();
    if (tid == 0) {
        float mx = -INFINITY;
        for (int j = 0; j < Sz; j++) mx = fmaxf(mx, zs[j]);
        float sum = 0.f;
        for (int j = 0; j < Sz; j++) sum += __expf(zs[j] - mx);
        s_mx = mx;
        s_sum = sum;
    }
    __syncthreads();
    if (tid < Sz)
        out[b * Sz + tid] = __expf(zs[tid] - s_mx) * __fdividef(1.f, s_sum);
}

// ---------------- launch ----------------
extern "C" void kernel_launch(void* const* d_in, const int* in_sizes, int n_in,
                              void* d_out, int out_size) {
    const float* x    = (const float*)d_in[0];
    const float* Wih  = (const float*)d_in[1];
    const float* Whh  = (const float*)d_in[2];
    const float* bih  = (const float*)d_in[3];
    const float* bhh  = (const float*)d_in[4];
    const float* wlin = (const float*)d_in[5];
    const float* blin = (const float*)d_in[6];
    const float* W2   = (const float*)d_in[7];
    const float* b2   = (const float*)d_in[8];
    const float* W3   = (const float*)d_in[9];
    const float* b3   = (const float*)d_in[10];
    float* out = (float*)d_out;
    (void)in_sizes; (void)n_in; (void)out_size;

    cudaFuncSetAttribute(lstm_kernel,
                         cudaFuncAttributeMaxDynamicSharedMemorySize, SMEM_BYTES);

    prep_kernel<<<512, 256>>>(Wih, Whh, bih, bhh, W2);
    lstm_kernel<<<NBLK, NTH, SMEM_BYTES>>>(x, wlin, blin);
    sort_kernel<<<Bz, 128>>>();
    mlp1_kernel<<<NCHUNK, 256>>>();
    reduce_kernel<<<Bz, 256>>>(b2);
    mlp2_kernel<<<Bz, 128>>>(W3, b3, out);
}

// round 6
// speedup vs baseline: 1.9172x; 1.9168x over previous
#include <cuda_runtime.h>
#include <cuda_bf16.h>
#include <math.h>

#define Bz 64
#define Tz 128
#define Sz 100
typedef unsigned int u32; typedef unsigned short u16;

// ---- LSTM mma config ----
#define OB 0
#define PB 72960            // bytes per B precision image (240 n * 304B)
#define OA 145920           // A_hi (8 rowgrp * 9 ks * 512B = 36864)
#define OAL 182784          // A_lo
#define OWL 219648          // w_lin[120]
#define SMEMT 220160
#define BPACK_U16 (2 * 2 * 240 * 152)
// MLP1
#define KCH 79
#define NCHUNK 128

__device__ u16   g_Bpack[BPACK_U16];        // [rank][prec][n][152] permuted bf16
__device__ float g_W2t[10000 * 256];
__device__ float g_spart[2 * 6400];
__device__ float g_foo[Bz * Sz * Sz];
__device__ float g_part[NCHUNK * Bz * 256];
__device__ float g_z1[Bz * 256];

__device__ __forceinline__ float sigm(float x){ return __fdividef(1.f, 1.f + __expf(-x)); }
__device__ __forceinline__ float tanh_fast(float x){ return __fdividef(2.f, 1.f + __expf(-2.f*x)) - 1.f; }
__device__ __forceinline__ void split2(float v, u16& h, u16& l){
    __nv_bfloat16 bh = __float2bfloat16(v);
    float r = v - __bfloat162float(bh);
    __nv_bfloat16 bl = __float2bfloat16(r);
    h = *reinterpret_cast<u16*>(&bh); l = *reinterpret_cast<u16*>(&bl);
}
__device__ __forceinline__ u32 smaddr(const void* p){
    u32 a; asm("{ .reg .u64 t; cvta.to.shared.u64 t, %1; cvt.u32.u64 %0, t; }":"=r"(a):"l"(p)); return a;
}
__device__ __forceinline__ u32 mapa_peer(u32 la, u32 pr){
    u32 r; asm("mapa.shared::cluster.u32 %0, %1, %2;":"=r"(r):"r"(la),"r"(pr)); return r;
}
#define CSYNC() do{ asm volatile("barrier.cluster.arrive.aligned;":::"memory"); \
                    asm volatile("barrier.cluster.wait.aligned;":::"memory"); }while(0)
#define MMAOP(d, a, b) asm volatile( \
    "mma.sync.aligned.m16n8k16.row.col.f32.bf16.bf16.f32 {%0,%1,%2,%3},{%4,%5,%6,%7},{%8,%9},{%0,%1,%2,%3};" \
    : "+f"((d)[0]), "+f"((d)[1]), "+f"((d)[2]), "+f"((d)[3]) \
    : "r"((a).x),"r"((a).y),"r"((a).z),"r"((a).w), "r"((b).x),"r"((b).y))

// in-tile u16 position for element (row%16, k%16) in fragment-linear layout
#define TPOS(rw, kk) ((((rw)&7)*4 + (((kk)&7)>>1))*16 + ((((kk)>>3)&1)*2 + (((rw)>>3)&1))*4 + ((kk)&1)*2)

// ---------------- prep: permuted bf16 hi/lo B images + W2t ----------------
__global__ void prep_kernel(const float* __restrict__ Wih, const float* __restrict__ Whh,
                            const float* __restrict__ bih, const float* __restrict__ bhh,
                            const float* __restrict__ W2) {
    int idx = blockIdx.x * blockDim.x + threadIdx.x, stride = gridDim.x * blockDim.x;
    for (int i = idx; i < 2 * 240 * 144; i += stride) {
        int k = i % 144, n = (i / 144) % 240, rank = i / (144 * 240);
        int g = n & 3, c = n >> 2;
        int j = g * 120 + rank * 60 + c;
        float v = 0.f;
        if (k < 16) v = Wih[j * 16 + k];
        else if (k < 136) v = Whh[j * 120 + (k - 16)];
        else if (k == 136) v = bih[j] + bhh[j];
        u16 hh, ll; split2(v, hh, ll);
        int pos = (k >> 4) * 16 + (((k & 15) & 7) >> 1) * 4 + (((k & 15) >> 3) & 1) * 2 + (k & 1);
        size_t b0 = ((size_t)(rank * 2) * 240 + n) * 152 + pos;
        g_Bpack[b0] = hh;
        g_Bpack[b0 + 240 * 152] = ll;
    }
    for (int i = idx; i < 10000 * 256; i += stride) {
        int k = i >> 8, o = i & 255;
        g_W2t[i] = W2[o * 10000 + k];
    }
}

// ---------------- warp-MMA LSTM ----------------
__device__ __forceinline__ void store_x(char* sm, const float* x, int pair, int tid, int tstep) {
    int lr = tid >> 1;
    int xrow = pair * 128 + lr;
    int xb = xrow / Sz, xs = xrow - xb * Sz;
    const float4* xp = (const float4*)(x + (((size_t)xb * Tz + tstep) * Sz + xs) * 16 + (tid & 1) * 8);
    float4 v0 = xp[0], v1 = xp[1];
    float xv[8] = {v0.x, v0.y, v0.z, v0.w, v1.x, v1.y, v1.z, v1.w};
    u32 base = (u32)((lr >> 4) * 9) * 512;
    #pragma unroll
    for (int j = 0; j < 4; j++) {
        int k = (tid & 1) * 8 + 2 * j;
        u16 h0, l0, h1, l1;
        split2(xv[2*j], h0, l0); split2(xv[2*j+1], h1, l1);
        u32 off = base + (u32)(((lr & 7) * 4 + ((k & 7) >> 1)) * 16 + (((k >> 3) & 1) * 2 + ((lr >> 3) & 1)) * 4);
        *(u32*)(sm + OA + off)  = (u32)h0 | ((u32)h1 << 16);
        *(u32*)(sm + OAL + off) = (u32)l0 | ((u32)l1 << 16);
    }
}

__global__ void __launch_bounds__(256, 1) __cluster_dims__(2, 1, 1)
lstm_mma(const float* __restrict__ x, const float* __restrict__ w_lin) {
    extern __shared__ char sm[];
    const int tid = threadIdx.x, w = tid >> 5, lane = tid & 31;
    const int q = lane & 3, rq = lane >> 2;
    const u32 r = (u32)(blockIdx.x & 1);
    const int pair = blockIdx.x >> 1;
    const bool even = !(q & 1);

    // B copy (own rank image: hi+lo contiguous)
    {
        const int4* src = (const int4*)(g_Bpack + (size_t)r * (2 * 240 * 152));
        int4* dst = (int4*)sm;
        for (int i = tid; i < 145920 / 16; i += 256) dst[i] = src[i];
        int4 z = {0, 0, 0, 0};
        for (int i = tid; i < 73728 / 16; i += 256) ((int4*)(sm + OA))[i] = z;
        if (tid < 120) ((float*)(sm + OWL))[tid] = w_lin[tid];
    }
    __syncthreads();
    // bias-one column (k=136) + x(0)
    if (tid < 128) {
        int row = tid;
        u32 off = (u32)((row >> 4) * 9 + 8) * 512 + (u32)TPOS(row, 8);
        *(u16*)(sm + OA + off) = (u16)0x3F80;
    }
    store_x(sm, x, pair, tid, 0);
    CSYNC();

    const u32 remAhi = mapa_peer(smaddr(sm) + OA, 1u ^ r);
    const u32 remAlo = mapa_peer(smaddr(sm) + OAL, 1u ^ r);
    const float* wl = (const float*)(sm + OWL);
    const char* Ahb = sm + OA + w * 4608 + lane * 16;
    const char* Bpb = sm + rq * 304 + q * 8;

    float cst[30], sacc = 0.f;
    #pragma unroll
    for (int i = 0; i < 30; i++) cst[i] = 0.f;

    for (int t = 0; t < Tz; ++t) {
        float acc[30][4];
        #pragma unroll
        for (int nf = 0; nf < 30; nf++)
            #pragma unroll
            for (int i = 0; i < 4; i++) acc[nf][i] = 0.f;

        #pragma unroll 1
        for (int ks = 0; ks < 9; ks++) {
            uint4 ah = *(const uint4*)(Ahb + ks * 512);
            uint4 al = *(const uint4*)(Ahb + 36864 + ks * 512);
            const char* Bk = Bpb + ks * 32;
            #pragma unroll
            for (int nf = 0; nf < 30; nf++) {
                uint2 bh = *(const uint2*)(Bk + nf * 2432);
                uint2 bl = *(const uint2*)(Bk + PB + nf * 2432);
                MMAOP(acc[nf], ah, bh);
                MMAOP(acc[nf], al, bh);
                MMAOP(acc[nf], ah, bl);
            }
        }

        CSYNC();  // all cluster GEMM reads of A complete

        const bool last = (t == Tz - 1);
        #pragma unroll
        for (int nf = 0; nf < 30; nf++) {
            float s0 = __shfl_xor_sync(~0u, even ? acc[nf][2] : acc[nf][0], 1);
            float s1 = __shfl_xor_sync(~0u, even ? acc[nf][3] : acc[nf][1], 1);
            float gi = even ? acc[nf][0] : s0;
            float gf = even ? acc[nf][1] : s1;
            float gg = even ? s0 : acc[nf][2];
            float go = even ? s1 : acc[nf][3];
            float cc = fmaf(sigm(gf), cst[nf], sigm(gi) * tanh_fast(gg));
            cst[nf] = cc;
            float h = sigm(go) * tanh_fast(cc);
            int cidx = nf * 2 + (q >> 1);
            if (last) {
                sacc = fmaf(h, wl[(int)r * 60 + cidx], sacc);
            } else {
                int k = 16 + (int)r * 60 + cidx;
                u32 off = (u32)((w * 9 + (k >> 4)) * 512) +
                          (u32)((rq * 4 + ((k & 7) >> 1)) * 16 +
                                (((k >> 3) & 1) * 2 + (q & 1)) * 4 + (k & 1) * 2);
                u16 hh, ll; split2(h, hh, ll);
                *(u16*)(sm + OA + off) = hh;
                *(u16*)(sm + OAL + off) = ll;
                asm volatile("st.shared::cluster.u16 [%0], %1;" :: "r"(remAhi + off), "h"(hh) : "memory");
                asm volatile("st.shared::cluster.u16 [%0], %1;" :: "r"(remAlo + off), "h"(ll) : "memory");
            }
        }
        if (t + 1 < Tz) store_x(sm, x, pair, tid, t + 1);
        CSYNC();  // writes visible before next GEMM
    }

    sacc += __shfl_xor_sync(~0u, sacc, 2);
    if (q < 2) {
        int row = pair * 128 + w * 16 + rq + (q & 1) * 8;
        g_spart[(int)r * 6400 + row] = sacc;
    }
}

// ---------------- NeuralSort + softmax ----------------
__global__ void sort_kernel(const float* __restrict__ b_lin) {
    __shared__ float s_sm[Sz], rs_sm[Sz];
    int b = blockIdx.x, tid = threadIdx.x;
    if (tid < Sz) {
        int row = b * Sz + tid;
        s_sm[tid] = g_spart[row] + g_spart[6400 + row] + b_lin[0];
    }
    __syncthreads();
    if (tid < Sz) {
        float si = s_sm[tid], sum = 0.f;
        for (int j = 0; j < Sz; j++) sum += fabsf(si - s_sm[j]);
        rs_sm[tid] = sum;
    }
    __syncthreads();
    int warp = tid >> 5, lane = tid & 31;
    for (int i = warp; i < Sz; i += 4) {
        float scal = (float)(Sz - 1 - 2 * i);
        float v[4], e[4], mx = -INFINITY;
        #pragma unroll
        for (int c = 0; c < 4; c++) {
            int j = lane + 32 * c;
            v[c] = (j < Sz) ? (s_sm[j] * scal - rs_sm[j]) * 0.2f : -INFINITY;
            mx = fmaxf(mx, v[c]);
        }
        #pragma unroll
        for (int o = 16; o; o >>= 1) mx = fmaxf(mx, __shfl_xor_sync(~0u, mx, o));
        float sum = 0.f;
        #pragma unroll
        for (int c = 0; c < 4; c++) {
            int j = lane + 32 * c;
            e[c] = (j < Sz) ? __expf(v[c] - mx) : 0.f;
            sum += e[c];
        }
        #pragma unroll
        for (int o = 16; o; o >>= 1) sum += __shfl_xor_sync(~0u, sum, o);
        float inv = __fdividef(1.f, sum);
        #pragma unroll
        for (int c = 0; c < 4; c++) {
            int j = lane + 32 * c;
            if (j < Sz) g_foo[(size_t)b * (Sz * Sz) + i * Sz + j] = e[c] * inv;
        }
    }
}

// ---------------- MLP1 K-split GEMM ----------------
__global__ void __launch_bounds__(256) mlp1_kernel() {
    int c = blockIdx.x, tid = threadIdx.x;
    int k0 = c * KCH, kend = min(k0 + KCH, 10000);
    int bg = tid >> 5, og = tid & 31;
    float acc[8][8];
    #pragma unroll
    for (int i = 0; i < 8; i++)
        #pragma unroll
        for (int j = 0; j < 8; j++) acc[i][j] = 0.f;
    const float* fooB = g_foo + (size_t)(bg * 8) * 10000;
    for (int k = k0; k < kend; ++k) {
        float a[8];
        #pragma unroll
        for (int i = 0; i < 8; i++) a[i] = fooB[(size_t)i * 10000 + k];
        float4 w0 = *(const float4*)(g_W2t + (size_t)k * 256 + og * 8);
        float4 w1 = *(const float4*)(g_W2t + (size_t)k * 256 + og * 8 + 4);
        float wv[8] = {w0.x, w0.y, w0.z, w0.w, w1.x, w1.y, w1.z, w1.w};
        #pragma unroll
        for (int i = 0; i < 8; i++)
            #pragma unroll
            for (int j = 0; j < 8; j++) acc[i][j] = fmaf(a[i], wv[j], acc[i][j]);
    }
    #pragma unroll
    for (int i = 0; i < 8; i++)
        #pragma unroll
        for (int j = 0; j < 8; j++)
            g_part[((size_t)c * 64 + bg * 8 + i) * 256 + og * 8 + j] = acc[i][j];
}

__global__ void reduce_kernel(const float* __restrict__ b2) {
    int b = blockIdx.x, o = threadIdx.x;
    float s = b2[o];
    for (int c = 0; c < NCHUNK; ++c) s += g_part[((size_t)c * 64 + b) * 256 + o];
    g_z1[b * 256 + o] = fmaxf(s, 0.f);
}

__global__ void mlp2_kernel(const float* __restrict__ W3, const float* __restrict__ b3,
                            float* __restrict__ out) {
    __shared__ float z1s[256], zs[Sz], s_mx, s_sum;
    int b = blockIdx.x, tid = threadIdx.x;
    z1s[tid] = g_z1[b * 256 + tid];
    z1s[tid + 128] = g_z1[b * 256 + tid + 128];
    __syncthreads();
    if (tid < Sz) {
        float a = b3[tid];
        const float* wr = W3 + tid * 256;
        #pragma unroll 4
        for (int k = 0; k < 256; k++) a = fmaf(z1s[k], wr[k], a);
        zs[tid] = a;
    }
    __syncthreads();
    if (tid == 0) {
        float mx = -INFINITY;
        for (int j = 0; j < Sz; j++) mx = fmaxf(mx, zs[j]);
        float sum = 0.f;
        for (int j = 0; j < Sz; j++) sum += __expf(zs[j] - mx);
        s_mx = mx; s_sum = sum;
    }
    __syncthreads();
    if (tid < Sz) out[b * Sz + tid] = __expf(zs[tid] - s_mx) * __fdividef(1.f, s_sum);
}

extern "C" void kernel_launch(void* const* d_in, const int* in_sizes, int n_in,
                              void* d_out, int out_size) {
    const float* x    = (const float*)d_in[0];
    const float* Wih  = (const float*)d_in[1];
    const float* Whh  = (const float*)d_in[2];
    const float* bih  = (const float*)d_in[3];
    const float* bhh  = (const float*)d_in[4];
    const float* wlin = (const float*)d_in[5];
    const float* blin = (const float*)d_in[6];
    const float* W2   = (const float*)d_in[7];
    const float* b2   = (const float*)d_in[8];
    const float* W3   = (const float*)d_in[9];
    const float* b3   = (const float*)d_in[10];
    float* out = (float*)d_out;
    (void)in_sizes; (void)n_in; (void)out_size;

    cudaFuncSetAttribute(lstm_mma, cudaFuncAttributeMaxDynamicSharedMemorySize, SMEMT);
    prep_kernel<<<512, 256>>>(Wih, Whh, bih, bhh, W2);
    lstm_mma<<<100, 256, SMEMT>>>(x, wlin);
    sort_kernel<<<Bz, 128>>>(blin);
    mlp1_kernel<<<NCHUNK, 256>>>();
    reduce_kernel<<<Bz, 256>>>(b2);
    mlp2_kernel<<<Bz, 128>>>(W3, b3, out);
}

// round 7
// speedup vs baseline: 3.1109x; 1.6226x over previous
#include <cuda_runtime.h>
#include <cuda_fp16.h>
#include <math.h>

#define Bz 64
#define Tz 128
#define Sz 100
typedef unsigned int u32; typedef unsigned short u16;

// ---- LSTM mma config (fp16 2-pass, A in regs) ----
#define OB 0                 // B hi image: 240 n * 304B = 72960
#define OA 72960             // A_hi: 8 mtile * 9 ks * 512B = 36864
#define OAL 109824           // A_lo
#define OBIAS 146688         // 240 floats
#define OWL 147648           // 120 floats
#define SMEMT 148480
// MLP1
#define KCH 79
#define NCHUNK 128

__device__ u16   g_Bpack[2 * 240 * 152];   // [rank][n][152] fp16 weights, frag-permuted
__device__ float g_biasT[2 * 240];         // [rank][n] bias per gate col
__device__ float g_W2t[10000 * 256];
__device__ float g_spart[2 * 6400];
__device__ float g_foo[Bz * Sz * Sz];
__device__ float g_part[NCHUNK * Bz * 256];
__device__ float g_z1[Bz * 256];

__device__ __forceinline__ float sigm(float x){ return __fdividef(1.f, 1.f + __expf(-x)); }
__device__ __forceinline__ float tanh_fast(float x){ return __fdividef(2.f, 1.f + __expf(-2.f*x)) - 1.f; }
__device__ __forceinline__ void split2h(float v, u16& h, u16& l){
    __half hh = __float2half_rn(v);
    float r = v - __half2float(hh);
    __half ll = __float2half_rn(r);
    h = *reinterpret_cast<u16*>(&hh); l = *reinterpret_cast<u16*>(&ll);
}
__device__ __forceinline__ u32 smaddr(const void* p){
    u32 a; asm("{ .reg .u64 t; cvta.to.shared.u64 t, %1; cvt.u32.u64 %0, t; }":"=r"(a):"l"(p)); return a;
}
__device__ __forceinline__ u32 mapa_peer(u32 la, u32 pr){
    u32 r; asm("mapa.shared::cluster.u32 %0, %1, %2;":"=r"(r):"r"(la),"r"(pr)); return r;
}
#define CARRIVE() asm volatile("barrier.cluster.arrive.aligned;":::"memory")
#define CWAIT()   asm volatile("barrier.cluster.wait.aligned;":::"memory")
#define MMAOP(d, a, b) asm volatile( \
    "mma.sync.aligned.m16n8k16.row.col.f32.f16.f16.f32 {%0,%1,%2,%3},{%4,%5,%6,%7},{%8,%9},{%0,%1,%2,%3};" \
    : "+f"((d)[0]), "+f"((d)[1]), "+f"((d)[2]), "+f"((d)[3]) \
    : "r"((a).x),"r"((a).y),"r"((a).z),"r"((a).w), "r"((b).x),"r"((b).y))

// ---------------- prep ----------------
__global__ void prep_kernel(const float* __restrict__ Wih, const float* __restrict__ Whh,
                            const float* __restrict__ bih, const float* __restrict__ bhh,
                            const float* __restrict__ W2) {
    int idx = blockIdx.x * blockDim.x + threadIdx.x, stride = gridDim.x * blockDim.x;
    for (int i = idx; i < 2 * 240 * 144; i += stride) {
        int k = i % 144, n = (i / 144) % 240, rank = i / (144 * 240);
        int g = n & 3, c = n >> 2;
        int j = g * 120 + rank * 60 + c;
        float v = 0.f;
        if (k < 16) v = Wih[j * 16 + k];
        else if (k < 136) v = Whh[j * 120 + (k - 16)];
        __half hv = __float2half_rn(v);
        int pos = (k >> 4) * 16 + (((k & 15) & 7) >> 1) * 4 + (((k & 15) >> 3) & 1) * 2 + (k & 1);
        g_Bpack[((size_t)rank * 240 + n) * 152 + pos] = *reinterpret_cast<u16*>(&hv);
    }
    for (int i = idx; i < 2 * 240; i += stride) {
        int n = i % 240, rank = i / 240;
        int j = (n & 3) * 120 + rank * 60 + (n >> 2);
        g_biasT[i] = bih[j] + bhh[j];
    }
    for (int i = idx; i < 10000 * 256; i += stride) {
        int k = i >> 8, o = i & 255;
        g_W2t[i] = W2[o * 10000 + k];
    }
}

// ---------------- warp-MMA LSTM (fp16 2-pass) ----------------
__device__ __forceinline__ void write_x(char* sm, int tid, float4 v0, float4 v1) {
    int lr = tid >> 1;
    float xv[8] = {v0.x, v0.y, v0.z, v0.w, v1.x, v1.y, v1.z, v1.w};
    u32 base = (u32)((lr >> 4) * 9) * 512;
    #pragma unroll
    for (int j = 0; j < 4; j++) {
        int k = (tid & 1) * 8 + 2 * j;
        u16 h0, l0, h1, l1;
        split2h(xv[2*j], h0, l0); split2h(xv[2*j+1], h1, l1);
        u32 off = base + (u32)(((lr & 7) * 4 + ((k & 7) >> 1)) * 16 + (((k >> 3) & 1) * 2 + ((lr >> 3) & 1)) * 4);
        *(u32*)(sm + OA + off)  = (u32)h0 | ((u32)h1 << 16);
        *(u32*)(sm + OAL + off) = (u32)l0 | ((u32)l1 << 16);
    }
}

__global__ void __launch_bounds__(256, 1) __cluster_dims__(2, 1, 1)
lstm_mma(const float* __restrict__ x, const float* __restrict__ w_lin) {
    extern __shared__ char sm[];
    const int tid = threadIdx.x, w = tid >> 5, lane = tid & 31;
    const int q = lane & 3, rq = lane >> 2;
    const u32 r = (u32)(blockIdx.x & 1);
    const int pair = blockIdx.x >> 1;
    const bool even = !(q & 1);
    const int lr = tid >> 1;
    const int xrow = pair * 128 + lr;
    const int xb = xrow / Sz, xs = xrow - xb * Sz;
    const float* xrowp = x + ((size_t)xb * Tz * Sz + xs) * 16 + (tid & 1) * 8;

    // init: B copy, A zero, bias, w_lin
    {
        const int4* src = (const int4*)(g_Bpack + (size_t)r * (240 * 152));
        int4* dst = (int4*)sm;
        for (int i = tid; i < 72960 / 16; i += 256) dst[i] = src[i];
        int4 z = {0, 0, 0, 0};
        for (int i = tid; i < 73728 / 16; i += 256) ((int4*)(sm + OA))[i] = z;
        if (tid < 240) ((float*)(sm + OBIAS))[tid] = g_biasT[r * 240 + tid];
        if (tid < 120) ((float*)(sm + OWL))[tid] = w_lin[tid];
    }
    __syncthreads();
    {
        float4 v0 = *(const float4*)(xrowp);
        float4 v1 = *(const float4*)(xrowp + 4);
        write_x(sm, tid, v0, v1);
    }
    __syncthreads();

    const u32 remAhi = mapa_peer(smaddr(sm) + OA, 1u ^ r);
    const u32 remAlo = mapa_peer(smaddr(sm) + OAL, 1u ^ r);
    const float* wl = (const float*)(sm + OWL);
    const float* bias = (const float*)(sm + OBIAS);
    const char* Ahb = sm + OA + w * 4608 + lane * 16;
    const char* Bp = sm + rq * 304 + q * 8;

    float cst[30], sacc = 0.f;
    #pragma unroll
    for (int i = 0; i < 30; i++) cst[i] = 0.f;

    for (int t = 0; t < Tz; ++t) {
        const bool last = (t == Tz - 1);
        // prefetch x(t+1)
        float4 xv0, xv1;
        if (!last) {
            xv0 = *(const float4*)(xrowp + (size_t)(t + 1) * Sz * 16);
            xv1 = *(const float4*)(xrowp + (size_t)(t + 1) * Sz * 16 + 4);
        }
        // snapshot A into registers
        uint4 ah[9], al[9];
        #pragma unroll
        for (int ks = 0; ks < 9; ks++) {
            ah[ks] = *(const uint4*)(Ahb + ks * 512);
            al[ks] = *(const uint4*)(Ahb + 36864 + ks * 512);
        }
        CARRIVE();   // cluster may begin writing h(t+1) once everyone snapshotted

        #pragma unroll
        for (int nf = 0; nf < 30; nf++) {
            const char* Bn = Bp + nf * 2432;
            float aA[4] = {0.f, 0.f, 0.f, 0.f};
            float aB[4] = {0.f, 0.f, 0.f, 0.f};
            #pragma unroll
            for (int ks = 0; ks < 9; ks++) {
                uint2 bh = *(const uint2*)(Bn + ks * 32);
                MMAOP(aA, ah[ks], bh);
                MMAOP(aB, al[ks], bh);
            }
            if (nf == 0) CWAIT();   // hidden under nf0's MMAs
            float2 bv = *(const float2*)(bias + nf * 8 + 2 * q);
            float d0 = aA[0] + aB[0] + bv.x;
            float d1 = aA[1] + aB[1] + bv.y;
            float d2 = aA[2] + aB[2] + bv.x;
            float d3 = aA[3] + aB[3] + bv.y;
            float s0 = __shfl_xor_sync(~0u, even ? d2 : d0, 1);
            float s1 = __shfl_xor_sync(~0u, even ? d3 : d1, 1);
            float gi = even ? d0 : s0;
            float gf = even ? d1 : s1;
            float gg = even ? s0 : d2;
            float go = even ? s1 : d3;
            float cc = fmaf(sigm(gf), cst[nf], sigm(gi) * tanh_fast(gg));
            cst[nf] = cc;
            float h = sigm(go) * tanh_fast(cc);
            int cidx = nf * 2 + (q >> 1);
            if (last) {
                sacc = fmaf(h, wl[(int)r * 60 + cidx], sacc);
            } else {
                int k = 16 + (int)r * 60 + cidx;
                u32 off = (u32)((w * 9 + (k >> 4)) * 512) +
                          (u32)((rq * 4 + ((k & 7) >> 1)) * 16 +
                                (((k >> 3) & 1) * 2 + (q & 1)) * 4 + (k & 1) * 2);
                u16 hh, ll; split2h(h, hh, ll);
                *(u16*)(sm + OA + off) = hh;
                *(u16*)(sm + OAL + off) = ll;
                asm volatile("st.shared::cluster.u16 [%0], %1;" :: "r"(remAhi + off), "h"(hh) : "memory");
                asm volatile("st.shared::cluster.u16 [%0], %1;" :: "r"(remAlo + off), "h"(ll) : "memory");
            }
        }
        if (!last) write_x(sm, tid, xv0, xv1);
        CARRIVE();   // all writes of this step issued
        CWAIT();     // visible cluster-wide before next snapshot
    }

    sacc += __shfl_xor_sync(~0u, sacc, 2);
    if (q < 2) {
        int row = pair * 128 + w * 16 + rq + (q & 1) * 8;
        g_spart[(int)r * 6400 + row] = sacc;
    }
}

// ---------------- NeuralSort + softmax ----------------
__global__ void sort_kernel(const float* __restrict__ b_lin) {
    __shared__ float s_sm[Sz], rs_sm[Sz];
    int b = blockIdx.x, tid = threadIdx.x;
    if (tid < Sz) {
        int row = b * Sz + tid;
        s_sm[tid] = g_spart[row] + g_spart[6400 + row] + b_lin[0];
    }
    __syncthreads();
    if (tid < Sz) {
        float si = s_sm[tid], sum = 0.f;
        for (int j = 0; j < Sz; j++) sum += fabsf(si - s_sm[j]);
        rs_sm[tid] = sum;
    }
    __syncthreads();
    int warp = tid >> 5, lane = tid & 31;
    for (int i = warp; i < Sz; i += 4) {
        float scal = (float)(Sz - 1 - 2 * i);
        float v[4], e[4], mx = -INFINITY;
        #pragma unroll
        for (int c = 0; c < 4; c++) {
            int j = lane + 32 * c;
            v[c] = (j < Sz) ? (s_sm[j] * scal - rs_sm[j]) * 0.2f : -INFINITY;
            mx = fmaxf(mx, v[c]);
        }
        #pragma unroll
        for (int o = 16; o; o >>= 1) mx = fmaxf(mx, __shfl_xor_sync(~0u, mx, o));
        float sum = 0.f;
        #pragma unroll
        for (int c = 0; c < 4; c++) {
            int j = lane + 32 * c;
            e[c] = (j < Sz) ? __expf(v[c] - mx) : 0.f;
            sum += e[c];
        }
        #pragma unroll
        for (int o = 16; o; o >>= 1) sum += __shfl_xor_sync(~0u, sum, o);
        float inv = __fdividef(1.f, sum);
        #pragma unroll
        for (int c = 0; c < 4; c++) {
            int j = lane + 32 * c;
            if (j < Sz) g_foo[(size_t)b * (Sz * Sz) + i * Sz + j] = e[c] * inv;
        }
    }
}

// ---------------- MLP1 K-split GEMM ----------------
__global__ void __launch_bounds__(256) mlp1_kernel() {
    int c = blockIdx.x, tid = threadIdx.x;
    int k0 = c * KCH, kend = min(k0 + KCH, 10000);
    int bg = tid >> 5, og = tid & 31;
    float acc[8][8];
    #pragma unroll
    for (int i = 0; i < 8; i++)
        #pragma unroll
        for (int j = 0; j < 8; j++) acc[i][j] = 0.f;
    const float* fooB = g_foo + (size_t)(bg * 8) * 10000;
    for (int k = k0; k < kend; ++k) {
        float a[8];
        #pragma unroll
        for (int i = 0; i < 8; i++) a[i] = fooB[(size_t)i * 10000 + k];
        float4 w0 = *(const float4*)(g_W2t + (size_t)k * 256 + og * 8);
        float4 w1 = *(const float4*)(g_W2t + (size_t)k * 256 + og * 8 + 4);
        float wv[8] = {w0.x, w0.y, w0.z, w0.w, w1.x, w1.y, w1.z, w1.w};
        #pragma unroll
        for (int i = 0; i < 8; i++)
            #pragma unroll
            for (int j = 0; j < 8; j++) acc[i][j] = fmaf(a[i], wv[j], acc[i][j]);
    }
    #pragma unroll
    for (int i = 0; i < 8; i++)
        #pragma unroll
        for (int j = 0; j < 8; j++)
            g_part[((size_t)c * 64 + bg * 8 + i) * 256 + og * 8 + j] = acc[i][j];
}

__global__ void reduce_kernel(const float* __restrict__ b2) {
    int b = blockIdx.x, o = threadIdx.x;
    float s = b2[o];
    for (int c = 0; c < NCHUNK; ++c) s += g_part[((size_t)c * 64 + b) * 256 + o];
    g_z1[b * 256 + o] = fmaxf(s, 0.f);
}

__global__ void mlp2_kernel(const float* __restrict__ W3, const float* __restrict__ b3,
                            float* __restrict__ out) {
    __shared__ float z1s[256], zs[Sz], s_mx, s_sum;
    int b = blockIdx.x, tid = threadIdx.x;
    z1s[tid] = g_z1[b * 256 + tid];
    z1s[tid + 128] = g_z1[b * 256 + tid + 128];
    __syncthreads();
    if (tid < Sz) {
        float a = b3[tid];
        const float* wr = W3 + tid * 256;
        #pragma unroll 4
        for (int k = 0; k < 256; k++) a = fmaf(z1s[k], wr[k], a);
        zs[tid] = a;
    }
    __syncthreads();
    if (tid == 0) {
        float mx = -INFINITY;
        for (int j = 0; j < Sz; j++) mx = fmaxf(mx, zs[j]);
        float sum = 0.f;
        for (int j = 0; j < Sz; j++) sum += __expf(zs[j] - mx);
        s_mx = mx; s_sum = sum;
    }
    __syncthreads();
    if (tid < Sz) out[b * Sz + tid] = __expf(zs[tid] - s_mx) * __fdividef(1.f, s_sum);
}

extern "C" void kernel_launch(void* const* d_in, const int* in_sizes, int n_in,
                              void* d_out, int out_size) {
    const float* x    = (const float*)d_in[0];
    const float* Wih  = (const float*)d_in[1];
    const float* Whh  = (const float*)d_in[2];
    const float* bih  = (const float*)d_in[3];
    const float* bhh  = (const float*)d_in[4];
    const float* wlin = (const float*)d_in[5];
    const float* blin = (const float*)d_in[6];
    const float* W2   = (const float*)d_in[7];
    const float* b2   = (const float*)d_in[8];
    const float* W3   = (const float*)d_in[9];
    const float* b3   = (const float*)d_in[10];
    float* out = (float*)d_out;
    (void)in_sizes; (void)n_in; (void)out_size;

    cudaFuncSetAttribute(lstm_mma, cudaFuncAttributeMaxDynamicSharedMemorySize, SMEMT);
    prep_kernel<<<512, 256>>>(Wih, Whh, bih, bhh, W2);
    lstm_mma<<<100, 256, SMEMT>>>(x, wlin);
    sort_kernel<<<Bz, 128>>>(blin);
    mlp1_kernel<<<NCHUNK, 256>>>();
    reduce_kernel<<<Bz, 256>>>(b2);
    mlp2_kernel<<<Bz, 128>>>(W3, b3, out);
}

// round 8
// speedup vs baseline: 3.5413x; 1.1383x over previous
#include <cuda_runtime.h>
#include <cuda_fp16.h>
#include <math.h>

#define Bz 64
#define Tz 128
#define Sz 100
typedef unsigned int u32; typedef unsigned short u16;

// ---- LSTM mma config (fp16 2-pass, A in regs) ----
#define OB 0                 // B hi image: 240 n * 304B = 72960
#define OA 72960             // A_hi: 8 mtile * 9 ks * 512B = 36864
#define OAL 109824           // A_lo
#define OBIAS 146688         // 240 floats
#define OWL 147648           // 120 floats
#define SMEMT 148480
// MLP1
#define KCH 79
#define NCHUNK 128

__device__ u16   g_Bpack[2 * 240 * 152];   // [rank][n][152] fp16 weights, frag-permuted
__device__ float g_biasT[2 * 240];         // [rank][n] bias per gate col
__device__ float g_W2t[10000 * 256];
__device__ float g_spart[2 * 6400];
__device__ float g_foo[Bz * Sz * Sz];
__device__ float g_part[NCHUNK * Bz * 256];
__device__ float g_z1[Bz * 256];

__device__ __forceinline__ float tanh_a(float x){
    float y; asm("tanh.approx.f32 %0, %1;" : "=f"(y) : "f"(x)); return y;
}
__device__ __forceinline__ float sigm(float x){ return __fdividef(1.f, 1.f + __expf(-x)); }
__device__ __forceinline__ void split2h(float v, u16& h, u16& l){
    __half hh = __float2half_rn(v);
    float r = v - __half2float(hh);
    __half ll = __float2half_rn(r);
    h = *reinterpret_cast<u16*>(&hh); l = *reinterpret_cast<u16*>(&ll);
}
__device__ __forceinline__ u32 smaddr(const void* p){
    u32 a; asm("{ .reg .u64 t; cvta.to.shared.u64 t, %1; cvt.u32.u64 %0, t; }":"=r"(a):"l"(p)); return a;
}
__device__ __forceinline__ u32 mapa_peer(u32 la, u32 pr){
    u32 r; asm("mapa.shared::cluster.u32 %0, %1, %2;":"=r"(r):"r"(la),"r"(pr)); return r;
}
#define CARRIVE() asm volatile("barrier.cluster.arrive.aligned;":::"memory")
#define CWAIT()   asm volatile("barrier.cluster.wait.aligned;":::"memory")
#define MMAOP(d, a, b) asm volatile( \
    "mma.sync.aligned.m16n8k16.row.col.f32.f16.f16.f32 {%0,%1,%2,%3},{%4,%5,%6,%7},{%8,%9},{%0,%1,%2,%3};" \
    : "+f"((d)[0]), "+f"((d)[1]), "+f"((d)[2]), "+f"((d)[3]) \
    : "r"((a).x),"r"((a).y),"r"((a).z),"r"((a).w), "r"((b).x),"r"((b).y))

// ---------------- prep ----------------
__global__ void prep_kernel(const float* __restrict__ Wih, const float* __restrict__ Whh,
                            const float* __restrict__ bih, const float* __restrict__ bhh,
                            const float* __restrict__ W2) {
    int idx = blockIdx.x * blockDim.x + threadIdx.x, stride = gridDim.x * blockDim.x;
    for (int i = idx; i < 2 * 240 * 144; i += stride) {
        int k = i % 144, n = (i / 144) % 240, rank = i / (144 * 240);
        int g = n & 3, c = n >> 2;
        int j = g * 120 + rank * 60 + c;
        float v = 0.f;
        if (k < 16) v = Wih[j * 16 + k];
        else if (k < 136) v = Whh[j * 120 + (k - 16)];
        __half hv = __float2half_rn(v);
        int pos = (k >> 4) * 16 + (((k & 15) & 7) >> 1) * 4 + (((k & 15) >> 3) & 1) * 2 + (k & 1);
        g_Bpack[((size_t)rank * 240 + n) * 152 + pos] = *reinterpret_cast<u16*>(&hv);
    }
    for (int i = idx; i < 2 * 240; i += stride) {
        int n = i % 240, rank = i / 240;
        int j = (n & 3) * 120 + rank * 60 + (n >> 2);
        g_biasT[i] = bih[j] + bhh[j];
    }
    for (int i = idx; i < 10000 * 256; i += stride) {
        int k = i >> 8, o = i & 255;
        g_W2t[i] = W2[o * 10000 + k];
    }
}

// ---------------- warp-MMA LSTM (fp16 2-pass, tanh.approx epilogue) ----------------
__device__ __forceinline__ void write_x(char* sm, int tid, float4 v0, float4 v1) {
    int lr = tid >> 1;
    float xv[8] = {v0.x, v0.y, v0.z, v0.w, v1.x, v1.y, v1.z, v1.w};
    u32 base = (u32)((lr >> 4) * 9) * 512;
    #pragma unroll
    for (int j = 0; j < 4; j++) {
        int k = (tid & 1) * 8 + 2 * j;
        u16 h0, l0, h1, l1;
        split2h(xv[2*j], h0, l0); split2h(xv[2*j+1], h1, l1);
        u32 off = base + (u32)(((lr & 7) * 4 + ((k & 7) >> 1)) * 16 + (((k >> 3) & 1) * 2 + ((lr >> 3) & 1)) * 4);
        *(u32*)(sm + OA + off)  = (u32)h0 | ((u32)h1 << 16);
        *(u32*)(sm + OAL + off) = (u32)l0 | ((u32)l1 << 16);
    }
}

__global__ void __launch_bounds__(256, 1) __cluster_dims__(2, 1, 1)
lstm_mma(const float* __restrict__ x, const float* __restrict__ w_lin) {
    extern __shared__ char sm[];
    const int tid = threadIdx.x, w = tid >> 5, lane = tid & 31;
    const int q = lane & 3, rq = lane >> 2;
    const u32 r = (u32)(blockIdx.x & 1);
    const int pair = blockIdx.x >> 1;
    const bool even = !(q & 1);
    const int lr = tid >> 1;
    const int xrow = pair * 128 + lr;
    const int xb = xrow / Sz, xs = xrow - xb * Sz;
    const float* xrowp = x + ((size_t)xb * Tz * Sz + xs) * 16 + (tid & 1) * 8;

    // init: B copy, A zero, bias, w_lin
    {
        const int4* src = (const int4*)(g_Bpack + (size_t)r * (240 * 152));
        int4* dst = (int4*)sm;
        for (int i = tid; i < 72960 / 16; i += 256) dst[i] = src[i];
        int4 z = {0, 0, 0, 0};
        for (int i = tid; i < 73728 / 16; i += 256) ((int4*)(sm + OA))[i] = z;
        if (tid < 240) ((float*)(sm + OBIAS))[tid] = g_biasT[r * 240 + tid];
        if (tid < 120) ((float*)(sm + OWL))[tid] = w_lin[tid];
    }
    __syncthreads();
    {
        float4 v0 = *(const float4*)(xrowp);
        float4 v1 = *(const float4*)(xrowp + 4);
        write_x(sm, tid, v0, v1);
    }
    __syncthreads();

    const u32 remAhi = mapa_peer(smaddr(sm) + OA, 1u ^ r);
    const u32 remAlo = mapa_peer(smaddr(sm) + OAL, 1u ^ r);
    const float* wl = (const float*)(sm + OWL);
    const float* bias = (const float*)(sm + OBIAS);
    const char* Ahb = sm + OA + w * 4608 + lane * 16;
    const char* Bp = sm + rq * 304 + q * 8;

    float cst[30], sacc = 0.f;
    #pragma unroll
    for (int i = 0; i < 30; i++) cst[i] = 0.f;

    for (int t = 0; t < Tz; ++t) {
        const bool last = (t == Tz - 1);
        // prefetch x(t+1)
        float4 xv0, xv1;
        if (!last) {
            xv0 = *(const float4*)(xrowp + (size_t)(t + 1) * Sz * 16);
            xv1 = *(const float4*)(xrowp + (size_t)(t + 1) * Sz * 16 + 4);
        }
        // snapshot A into registers
        uint4 ah[9], al[9];
        #pragma unroll
        for (int ks = 0; ks < 9; ks++) {
            ah[ks] = *(const uint4*)(Ahb + ks * 512);
            al[ks] = *(const uint4*)(Ahb + 36864 + ks * 512);
        }
        CARRIVE();   // cluster may begin writing h(t+1) once everyone snapshotted

        #pragma unroll
        for (int nf = 0; nf < 30; nf++) {
            const char* Bn = Bp + nf * 2432;
            float aA[4] = {0.f, 0.f, 0.f, 0.f};
            float aB[4] = {0.f, 0.f, 0.f, 0.f};
            #pragma unroll
            for (int ks = 0; ks < 9; ks++) {
                uint2 bh = *(const uint2*)(Bn + ks * 32);
                MMAOP(aA, ah[ks], bh);
                MMAOP(aB, al[ks], bh);
            }
            if (nf == 0) CWAIT();   // hidden under nf0's MMAs
            float2 bv = *(const float2*)(bias + nf * 8 + 2 * q);
            float d0 = aA[0] + aB[0] + bv.x;
            float d1 = aA[1] + aB[1] + bv.y;
            float d2 = aA[2] + aB[2] + bv.x;
            float d3 = aA[3] + aB[3] + bv.y;
            float s0 = __shfl_xor_sync(~0u, even ? d2 : d0, 1);
            float s1 = __shfl_xor_sync(~0u, even ? d3 : d1, 1);
            float gi = even ? d0 : s0;
            float gf = even ? d1 : s1;
            float gg = even ? s0 : d2;
            float go = even ? s1 : d3;
            // activations via hardware tanh: sigm(x) = 0.5*tanh(0.5x)+0.5
            float si = fmaf(tanh_a(0.5f * gi), 0.5f, 0.5f);
            float sf = fmaf(tanh_a(0.5f * gf), 0.5f, 0.5f);
            float sg = tanh_a(gg);
            float so = fmaf(tanh_a(0.5f * go), 0.5f, 0.5f);
            float cc = fmaf(sf, cst[nf], si * sg);
            cst[nf] = cc;
            float h = so * tanh_a(cc);
            int cidx = nf * 2 + (q >> 1);
            if (last) {
                sacc = fmaf(h, wl[(int)r * 60 + cidx], sacc);
            } else {
                int k = 16 + (int)r * 60 + cidx;
                u32 off = (u32)((w * 9 + (k >> 4)) * 512) +
                          (u32)((rq * 4 + ((k & 7) >> 1)) * 16 +
                                (((k >> 3) & 1) * 2 + (q & 1)) * 4 + (k & 1) * 2);
                u16 hh, ll; split2h(h, hh, ll);
                *(u16*)(sm + OA + off) = hh;
                *(u16*)(sm + OAL + off) = ll;
                asm volatile("st.shared::cluster.u16 [%0], %1;" :: "r"(remAhi + off), "h"(hh) : "memory");
                asm volatile("st.shared::cluster.u16 [%0], %1;" :: "r"(remAlo + off), "h"(ll) : "memory");
            }
        }
        if (!last) write_x(sm, tid, xv0, xv1);
        CARRIVE();   // all writes of this step issued
        CWAIT();     // visible cluster-wide before next snapshot
    }

    sacc += __shfl_xor_sync(~0u, sacc, 2);
    if (q < 2) {
        int row = pair * 128 + w * 16 + rq + (q & 1) * 8;
        g_spart[(int)r * 6400 + row] = sacc;
    }
}

// ---------------- NeuralSort + softmax ----------------
__global__ void sort_kernel(const float* __restrict__ b_lin) {
    __shared__ float s_sm[Sz], rs_sm[Sz];
    int b = blockIdx.x, tid = threadIdx.x;
    if (tid < Sz) {
        int row = b * Sz + tid;
        s_sm[tid] = g_spart[row] + g_spart[6400 + row] + b_lin[0];
    }
    __syncthreads();
    if (tid < Sz) {
        float si = s_sm[tid], sum = 0.f;
        for (int j = 0; j < Sz; j++) sum += fabsf(si - s_sm[j]);
        rs_sm[tid] = sum;
    }
    __syncthreads();
    int warp = tid >> 5, lane = tid & 31;
    for (int i = warp; i < Sz; i += 4) {
        float scal = (float)(Sz - 1 - 2 * i);
        float v[4], e[4], mx = -INFINITY;
        #pragma unroll
        for (int c = 0; c < 4; c++) {
            int j = lane + 32 * c;
            v[c] = (j < Sz) ? (s_sm[j] * scal - rs_sm[j]) * 0.2f : -INFINITY;
            mx = fmaxf(mx, v[c]);
        }
        #pragma unroll
        for (int o = 16; o; o >>= 1) mx = fmaxf(mx, __shfl_xor_sync(~0u, mx, o));
        float sum = 0.f;
        #pragma unroll
        for (int c = 0; c < 4; c++) {
            int j = lane + 32 * c;
            e[c] = (j < Sz) ? __expf(v[c] - mx) : 0.f;
            sum += e[c];
        }
        #pragma unroll
        for (int o = 16; o; o >>= 1) sum += __shfl_xor_sync(~0u, sum, o);
        float inv = __fdividef(1.f, sum);
        #pragma unroll
        for (int c = 0; c < 4; c++) {
            int j = lane + 32 * c;
            if (j < Sz) g_foo[(size_t)b * (Sz * Sz) + i * Sz + j] = e[c] * inv;
        }
    }
}

// ---------------- MLP1 K-split GEMM ----------------
__global__ void __launch_bounds__(256) mlp1_kernel() {
    int c = blockIdx.x, tid = threadIdx.x;
    int k0 = c * KCH, kend = min(k0 + KCH, 10000);
    int bg = tid >> 5, og = tid & 31;
    float acc[8][8];
    #pragma unroll
    for (int i = 0; i < 8; i++)
        #pragma unroll
        for (int j = 0; j < 8; j++) acc[i][j] = 0.f;
    const float* fooB = g_foo + (size_t)(bg * 8) * 10000;
    int k = k0;
    for (; k + 2 <= kend; k += 2) {
        float a0[8], a1[8];
        #pragma unroll
        for (int i = 0; i < 8; i++) { a0[i] = fooB[(size_t)i * 10000 + k]; a1[i] = fooB[(size_t)i * 10000 + k + 1]; }
        float4 p0 = *(const float4*)(g_W2t + (size_t)k * 256 + og * 8);
        float4 p1 = *(const float4*)(g_W2t + (size_t)k * 256 + og * 8 + 4);
        float4 q0 = *(const float4*)(g_W2t + (size_t)(k + 1) * 256 + og * 8);
        float4 q1 = *(const float4*)(g_W2t + (size_t)(k + 1) * 256 + og * 8 + 4);
        float w0[8] = {p0.x, p0.y, p0.z, p0.w, p1.x, p1.y, p1.z, p1.w};
        float w1[8] = {q0.x, q0.y, q0.z, q0.w, q1.x, q1.y, q1.z, q1.w};
        #pragma unroll
        for (int i = 0; i < 8; i++)
            #pragma unroll
            for (int j = 0; j < 8; j++)
                acc[i][j] = fmaf(a1[i], w1[j], fmaf(a0[i], w0[j], acc[i][j]));
    }
    for (; k < kend; ++k) {
        float a[8];
        #pragma unroll
        for (int i = 0; i < 8; i++) a[i] = fooB[(size_t)i * 10000 + k];
        float4 w0 = *(const float4*)(g_W2t + (size_t)k * 256 + og * 8);
        float4 w1 = *(const float4*)(g_W2t + (size_t)k * 256 + og * 8 + 4);
        float wv[8] = {w0.x, w0.y, w0.z, w0.w, w1.x, w1.y, w1.z, w1.w};
        #pragma unroll
        for (int i = 0; i < 8; i++)
            #pragma unroll
            for (int j = 0; j < 8; j++) acc[i][j] = fmaf(a[i], wv[j], acc[i][j]);
    }
    #pragma unroll
    for (int i = 0; i < 8; i++)
        #pragma unroll
        for (int j = 0; j < 8; j++)
            g_part[((size_t)c * 64 + bg * 8 + i) * 256 + og * 8 + j] = acc[i][j];
}

__global__ void reduce_kernel(const float* __restrict__ b2) {
    int b = blockIdx.x, o = threadIdx.x;
    float s = b2[o];
    for (int c = 0; c < NCHUNK; ++c) s += g_part[((size_t)c * 64 + b) * 256 + o];
    g_z1[b * 256 + o] = fmaxf(s, 0.f);
}

__global__ void mlp2_kernel(const float* __restrict__ W3, const float* __restrict__ b3,
                            float* __restrict__ out) {
    __shared__ float z1s[256], zs[Sz], s_mx, s_sum;
    int b = blockIdx.x, tid = threadIdx.x;
    z1s[tid] = g_z1[b * 256 + tid];
    z1s[tid + 128] = g_z1[b * 256 + tid + 128];
    __syncthreads();
    if (tid < Sz) {
        float a = b3[tid];
        const float* wr = W3 + tid * 256;
        #pragma unroll 4
        for (int k = 0; k < 256; k++) a = fmaf(z1s[k], wr[k], a);
        zs[tid] = a;
    }
    __syncthreads();
    if (tid == 0) {
        float mx = -INFINITY;
        for (int j = 0; j < Sz; j++) mx = fmaxf(mx, zs[j]);
        float sum = 0.f;
        for (int j = 0; j < Sz; j++) sum += __expf(zs[j] - mx);
        s_mx = mx; s_sum = sum;
    }
    __syncthreads();
    if (tid < Sz) out[b * Sz + tid] = __expf(zs[tid] - s_mx) * __fdividef(1.f, s_sum);
}

extern "C" void kernel_launch(void* const* d_in, const int* in_sizes, int n_in,
                              void* d_out, int out_size) {
    const float* x    = (const float*)d_in[0];
    const float* Wih  = (const float*)d_in[1];
    const float* Whh  = (const float*)d_in[2];
    const float* bih  = (const float*)d_in[3];
    const float* bhh  = (const float*)d_in[4];
    const float* wlin = (const float*)d_in[5];
    const float* blin = (const float*)d_in[6];
    const float* W2   = (const float*)d_in[7];
    const float* b2   = (const float*)d_in[8];
    const float* W3   = (const float*)d_in[9];
    const float* b3   = (const float*)d_in[10];
    float* out = (float*)d_out;
    (void)in_sizes; (void)n_in; (void)out_size;

    cudaFuncSetAttribute(lstm_mma, cudaFuncAttributeMaxDynamicSharedMemorySize, SMEMT);
    prep_kernel<<<512, 256>>>(Wih, Whh, bih, bhh, W2);
    lstm_mma<<<100, 256, SMEMT>>>(x, wlin);
    sort_kernel<<<Bz, 128>>>(blin);
    mlp1_kernel<<<NCHUNK, 256>>>();
    reduce_kernel<<<Bz, 256>>>(b2);
    mlp2_kernel<<<Bz, 128>>>(W3, b3, out);
}

// round 10
// speedup vs baseline: 4.2699x; 1.2057x over previous
#include <cuda_runtime.h>
#include <cuda_fp16.h>
#include <math.h>

#define Bz 64
#define Tz 128
#define Sz 100
typedef unsigned int u32; typedef unsigned short u16;

// ---- LSTM mma config (fp16 single-pass, A in regs) ----
#define OB 0                 // B image: 240 n * 304B = 72960
#define OA 72960             // A: 8 mtile * 9 ks * 512B = 36864
#define OBIAS 109824         // 240 floats
#define OWL 110784           // 120 floats
#define SMEMT 111264
// MLP1
#define KCH 79
#define NCHUNK 128

__device__ u16   g_Bpack[2 * 240 * 152];   // [rank][n][152] fp16 weights, frag-permuted
__device__ float g_biasT[2 * 240];         // [rank][n] bias per gate col
__device__ float g_W2t[10000 * 256];
__device__ float g_spart[2 * 6400];
__device__ float g_foo[Bz * Sz * Sz];
__device__ float g_part[NCHUNK * Bz * 256];
__device__ float g_part2[8 * Bz * 256];
__device__ float g_z1[Bz * 256];

__device__ __forceinline__ float tanh_a(float x){
    float y; asm("tanh.approx.f32 %0, %1;" : "=f"(y) : "f"(x)); return y;
}
__device__ __forceinline__ u16 h2u(float v){
    __half hh = __float2half_rn(v);
    return *reinterpret_cast<u16*>(&hh);
}
__device__ __forceinline__ u32 smaddr(const void* p){
    u32 a; asm("{ .reg .u64 t; cvta.to.shared.u64 t, %1; cvt.u32.u64 %0, t; }":"=r"(a):"l"(p)); return a;
}
__device__ __forceinline__ u32 mapa_peer(u32 la, u32 pr){
    u32 r; asm("mapa.shared::cluster.u32 %0, %1, %2;":"=r"(r):"r"(la),"r"(pr)); return r;
}
#define CARRIVE() asm volatile("barrier.cluster.arrive.aligned;":::"memory")
#define CWAIT()   asm volatile("barrier.cluster.wait.aligned;":::"memory")
#define MMAOP(d, a, b) asm volatile( \
    "mma.sync.aligned.m16n8k16.row.col.f32.f16.f16.f32 {%0,%1,%2,%3},{%4,%5,%6,%7},{%8,%9},{%0,%1,%2,%3};" \
    : "+f"((d)[0]), "+f"((d)[1]), "+f"((d)[2]), "+f"((d)[3]) \
    : "r"((a).x),"r"((a).y),"r"((a).z),"r"((a).w), "r"((b).x),"r"((b).y))

// ---------------- prep: B pack + bias ----------------
__global__ void prep_kernel(const float* __restrict__ Wih, const float* __restrict__ Whh,
                            const float* __restrict__ bih, const float* __restrict__ bhh) {
    int idx = blockIdx.x * blockDim.x + threadIdx.x, stride = gridDim.x * blockDim.x;
    for (int i = idx; i < 2 * 240 * 144; i += stride) {
        int k = i % 144, n = (i / 144) % 240, rank = i / (144 * 240);
        int g = n & 3, c = n >> 2;
        int j = g * 120 + rank * 60 + c;
        float v = 0.f;
        if (k < 16) v = Wih[j * 16 + k];
        else if (k < 136) v = Whh[j * 120 + (k - 16)];
        int pos = (k >> 4) * 16 + (((k & 15) & 7) >> 1) * 4 + (((k & 15) >> 3) & 1) * 2 + (k & 1);
        g_Bpack[((size_t)rank * 240 + n) * 152 + pos] = h2u(v);
    }
    for (int i = idx; i < 2 * 240; i += stride) {
        int n = i % 240, rank = i / 240;
        int j = (n & 3) * 120 + rank * 60 + (n >> 2);
        g_biasT[i] = bih[j] + bhh[j];
    }
}

// ---------------- W2 transpose, smem-tiled ----------------
__global__ void w2t_kernel(const float* __restrict__ W2) {
    __shared__ float tile[32][33];
    int k0 = blockIdx.x * 32, o0 = blockIdx.y * 32;
    int tx = threadIdx.x, ty = threadIdx.y;
    int k = k0 + tx, o = o0 + ty;
    if (k < 10000) tile[ty][tx] = W2[(size_t)o * 10000 + k];
    __syncthreads();
    int kk = k0 + ty, oo = o0 + tx;
    if (kk < 10000) g_W2t[(size_t)kk * 256 + oo] = tile[tx][ty];
}

// ---------------- warp-MMA LSTM (fp16 single-pass) ----------------
__device__ __forceinline__ void write_x(char* sm, int tid, float4 v0, float4 v1) {
    int lr = tid >> 1;
    float xv[8] = {v0.x, v0.y, v0.z, v0.w, v1.x, v1.y, v1.z, v1.w};
    u32 base = (u32)((lr >> 4) * 9) * 512;
    #pragma unroll
    for (int j = 0; j < 4; j++) {
        int k = (tid & 1) * 8 + 2 * j;
        u32 off = base + (u32)(((lr & 7) * 4 + ((k & 7) >> 1)) * 16 + (((k >> 3) & 1) * 2 + ((lr >> 3) & 1)) * 4);
        *(u32*)(sm + OA + off) = (u32)h2u(xv[2*j]) | ((u32)h2u(xv[2*j+1]) << 16);
    }
}

__global__ void __launch_bounds__(256, 1) __cluster_dims__(2, 1, 1)
lstm_mma(const float* __restrict__ x, const float* __restrict__ w_lin) {
    extern __shared__ char sm[];
    const int tid = threadIdx.x, w = tid >> 5, lane = tid & 31;
    const int q = lane & 3, rq = lane >> 2;
    const u32 r = (u32)(blockIdx.x & 1);
    const int pair = blockIdx.x >> 1;
    const bool even = !(q & 1);
    const int lr = tid >> 1;
    const int xrow = pair * 128 + lr;
    const int xb = xrow / Sz, xs = xrow - xb * Sz;
    const float* xrowp = x + ((size_t)xb * Tz * Sz + xs) * 16 + (tid & 1) * 8;

    // init: B copy, A zero, bias, w_lin
    {
        const int4* src = (const int4*)(g_Bpack + (size_t)r * (240 * 152));
        int4* dst = (int4*)sm;
        for (int i = tid; i < 72960 / 16; i += 256) dst[i] = src[i];
        int4 z = {0, 0, 0, 0};
        for (int i = tid; i < 36864 / 16; i += 256) ((int4*)(sm + OA))[i] = z;
        if (tid < 240) ((float*)(sm + OBIAS))[tid] = g_biasT[r * 240 + tid];
        if (tid < 120) ((float*)(sm + OWL))[tid] = w_lin[tid];
    }
    __syncthreads();
    {
        float4 v0 = *(const float4*)(xrowp);
        float4 v1 = *(const float4*)(xrowp + 4);
        write_x(sm, tid, v0, v1);
    }
    __syncthreads();

    const u32 remA = mapa_peer(smaddr(sm) + OA, 1u ^ r);
    const float* wl = (const float*)(sm + OWL);
    const float* bias = (const float*)(sm + OBIAS);
    const char* Ahb = sm + OA + w * 4608 + lane * 16;
    const char* Bp = sm + rq * 304 + q * 8;

    float cst[30], sacc = 0.f;
    #pragma unroll
    for (int i = 0; i < 30; i++) cst[i] = 0.f;

    for (int t = 0; t < Tz; ++t) {
        const bool last = (t == Tz - 1);
        // prefetch x(t+1)
        float4 xv0, xv1;
        if (!last) {
            xv0 = *(const float4*)(xrowp + (size_t)(t + 1) * Sz * 16);
            xv1 = *(const float4*)(xrowp + (size_t)(t + 1) * Sz * 16 + 4);
        }
        // snapshot A into registers
        uint4 ah[9];
        #pragma unroll
        for (int ks = 0; ks < 9; ks++) ah[ks] = *(const uint4*)(Ahb + ks * 512);
        CARRIVE();   // cluster may begin writing h(t+1) once everyone snapshotted

        #pragma unroll
        for (int nf = 0; nf < 30; nf++) {
            const char* Bn = Bp + nf * 2432;
            float aA[4] = {0.f, 0.f, 0.f, 0.f};
            #pragma unroll
            for (int ks = 0; ks < 9; ks++) {
                uint2 bh = *(const uint2*)(Bn + ks * 32);
                MMAOP(aA, ah[ks], bh);
            }
            if (nf == 0) CWAIT();   // hidden under nf0's MMAs
            float2 bv = *(const float2*)(bias + nf * 8 + 2 * q);
            float d0 = aA[0] + bv.x;
            float d1 = aA[1] + bv.y;
            float d2 = aA[2] + bv.x;
            float d3 = aA[3] + bv.y;
            float s0 = __shfl_xor_sync(~0u, even ? d2 : d0, 1);
            float s1 = __shfl_xor_sync(~0u, even ? d3 : d1, 1);
            float gi = even ? d0 : s0;
            float gf = even ? d1 : s1;
            float gg = even ? s0 : d2;
            float go = even ? s1 : d3;
            float si = fmaf(tanh_a(0.5f * gi), 0.5f, 0.5f);
            float sf = fmaf(tanh_a(0.5f * gf), 0.5f, 0.5f);
            float sg = tanh_a(gg);
            float so = fmaf(tanh_a(0.5f * go), 0.5f, 0.5f);
            float cc = fmaf(sf, cst[nf], si * sg);
            cst[nf] = cc;
            float h = so * tanh_a(cc);
            int cidx = nf * 2 + (q >> 1);
            if (last) {
                sacc = fmaf(h, wl[(int)r * 60 + cidx], sacc);
            } else {
                int k = 16 + (int)r * 60 + cidx;
                u32 off = (u32)((w * 9 + (k >> 4)) * 512) +
                          (u32)((rq * 4 + ((k & 7) >> 1)) * 16 +
                                (((k >> 3) & 1) * 2 + (q & 1)) * 4 + (k & 1) * 2);
                u16 hh = h2u(h);
                *(u16*)(sm + OA + off) = hh;
                asm volatile("st.shared::cluster.u16 [%0], %1;" :: "r"(remA + off), "h"(hh) : "memory");
            }
        }
        if (!last) write_x(sm, tid, xv0, xv1);
        CARRIVE();   // all writes of this step issued
        CWAIT();     // visible cluster-wide before next snapshot
    }

    sacc += __shfl_xor_sync(~0u, sacc, 2);
    if (q < 2) {
        int row = pair * 128 + w * 16 + rq + (q & 1) * 8;
        g_spart[(int)r * 6400 + row] = sacc;
    }
}

// ---------------- NeuralSort + softmax ----------------
__global__ void sort_kernel(const float* __restrict__ b_lin) {
    __shared__ float s_sm[Sz], rs_sm[Sz];
    int b = blockIdx.x, tid = threadIdx.x;
    if (tid < Sz) {
        int row = b * Sz + tid;
        s_sm[tid] = g_spart[row] + g_spart[6400 + row] + b_lin[0];
    }
    __syncthreads();
    if (tid < Sz) {
        float si = s_sm[tid], sum = 0.f;
        for (int j = 0; j < Sz; j++) sum += fabsf(si - s_sm[j]);
        rs_sm[tid] = sum;
    }
    __syncthreads();
    int warp = tid >> 5, lane = tid & 31;
    for (int i = warp; i < Sz; i += 4) {
        float scal = (float)(Sz - 1 - 2 * i);
        float v[4], e[4], mx = -INFINITY;
        #pragma unroll
        for (int c = 0; c < 4; c++) {
            int j = lane + 32 * c;
            v[c] = (j < Sz) ? (s_sm[j] * scal - rs_sm[j]) * 0.2f : -INFINITY;
            mx = fmaxf(mx, v[c]);
        }
        #pragma unroll
        for (int o = 16; o; o >>= 1) mx = fmaxf(mx, __shfl_xor_sync(~0u, mx, o));
        float sum = 0.f;
        #pragma unroll
        for (int c = 0; c < 4; c++) {
            int j = lane + 32 * c;
            e[c] = (j < Sz) ? __expf(v[c] - mx) : 0.f;
            sum += e[c];
        }
        #pragma unroll
        for (int o = 16; o; o >>= 1) sum += __shfl_xor_sync(~0u, sum, o);
        float inv = __fdividef(1.f, sum);
        #pragma unroll
        for (int c = 0; c < 4; c++) {
            int j = lane + 32 * c;
            if (j < Sz) g_foo[(size_t)b * (Sz * Sz) + i * Sz + j] = e[c] * inv;
        }
    }
}

// ---------------- MLP1 K-split GEMM ----------------
__global__ void __launch_bounds__(256) mlp1_kernel() {
    int c = blockIdx.x, tid = threadIdx.x;
    int k0 = c * KCH, kend = min(k0 + KCH, 10000);
    int bg = tid >> 5, og = tid & 31;
    float acc[8][8];
    #pragma unroll
    for (int i = 0; i < 8; i++)
        #pragma unroll
        for (int j = 0; j < 8; j++) acc[i][j] = 0.f;
    const float* fooB = g_foo + (size_t)(bg * 8) * 10000;
    for (int k = k0; k < kend; ++k) {
        float a[8];
        #pragma unroll
        for (int i = 0; i < 8; i++) a[i] = fooB[(size_t)i * 10000 + k];
        float4 w0 = *(const float4*)(g_W2t + (size_t)k * 256 + og * 8);
        float4 w1 = *(const float4*)(g_W2t + (size_t)k * 256 + og * 8 + 4);
        float wv[8] = {w0.x, w0.y, w0.z, w0.w, w1.x, w1.y, w1.z, w1.w};
        #pragma unroll
        for (int i = 0; i < 8; i++)
            #pragma unroll
            for (int j = 0; j < 8; j++) acc[i][j] = fmaf(a[i], wv[j], acc[i][j]);
    }
    #pragma unroll
    for (int i = 0; i < 8; i++)
        #pragma unroll
        for (int j = 0; j < 8; j++)
            g_part[((size_t)c * 64 + bg * 8 + i) * 256 + og * 8 + j] = acc[i][j];
}

// ---------------- two-stage reduce + relu ----------------
__global__ void reduce1_kernel() {
    int b = blockIdx.x, cg = blockIdx.y, o = threadIdx.x;
    float s = 0.f;
    #pragma unroll 4
    for (int c = cg * 16; c < cg * 16 + 16; ++c)
        s += g_part[((size_t)c * 64 + b) * 256 + o];
    g_part2[((size_t)cg * 64 + b) * 256 + o] = s;
}
__global__ void reduce2_kernel(const float* __restrict__ b2) {
    int b = blockIdx.x, o = threadIdx.x;
    float s = b2[o];
    #pragma unroll
    for (int g = 0; g < 8; ++g) s += g_part2[((size_t)g * 64 + b) * 256 + o];
    g_z1[b * 256 + o] = fmaxf(s, 0.f);
}

__global__ void mlp2_kernel(const float* __restrict__ W3, const float* __restrict__ b3,
                            float* __restrict__ out) {
    __shared__ float z1s[256], zs[Sz], s_mx, s_sum;
    int b = blockIdx.x, tid = threadIdx.x;
    z1s[tid] = g_z1[b * 256 + tid];
    z1s[tid + 128] = g_z1[b * 256 + tid + 128];
    __syncthreads();
    if (tid < Sz) {
        float a = b3[tid];
        const float* wr = W3 + tid * 256;
        #pragma unroll 4
        for (int k = 0; k < 256; k++) a = fmaf(z1s[k], wr[k], a);
        zs[tid] = a;
    }
    __syncthreads();
    if (tid == 0) {
        float mx = -INFINITY;
        for (int j = 0; j < Sz; j++) mx = fmaxf(mx, zs[j]);
        float sum = 0.f;
        for (int j = 0; j < Sz; j++) sum += __expf(zs[j] - mx);
        s_mx = mx; s_sum = sum;
    }
    __syncthreads();
    if (tid < Sz) out[b * Sz + tid] = __expf(zs[tid] - s_mx) * __fdividef(1.f, s_sum);
}

extern "C" void kernel_launch(void* const* d_in, const int* in_sizes, int n_in,
                              void* d_out, int out_size) {
    const float* x    = (const float*)d_in[0];
    const float* Wih  = (const float*)d_in[1];
    const float* Whh  = (const float*)d_in[2];
    const float* bih  = (const float*)d_in[3];
    const float* bhh  = (const float*)d_in[4];
    const float* wlin = (const float*)d_in[5];
    const float* blin = (const float*)d_in[6];
    const float* W2   = (const float*)d_in[7];
    const float* b2   = (const float*)d_in[8];
    const float* W3   = (const float*)d_in[9];
    const float* b3   = (const float*)d_in[10];
    float* out = (float*)d_out;
    (void)in_sizes; (void)n_in; (void)out_size;

    cudaFuncSetAttribute(lstm_mma, cudaFuncAttributeMaxDynamicSharedMemorySize, SMEMT);
    prep_kernel<<<256, 256>>>(Wih, Whh, bih, bhh);
    w2t_kernel<<<dim3(313, 8), dim3(32, 32)>>>(W2);
    lstm_mma<<<100, 256, SMEMT>>>(x, wlin);
    sort_kernel<<<Bz, 128>>>(blin);
    mlp1_kernel<<<NCHUNK, 256>>>();
    reduce1_kernel<<<dim3(Bz, 8), 256>>>();
    reduce2_kernel<<<Bz, 256>>>(b2);
    mlp2_kernel<<<Bz, 128>>>(W3, b3, out);
}

// round 11
// speedup vs baseline: 5.5666x; 1.3037x over previous
#include <cuda_runtime.h>
#include <cuda_fp16.h>
#include <math.h>

#define Bz 64
#define Tz 128
#define Sz 100
typedef unsigned int u32; typedef unsigned short u16;

// ---- LSTM mma config (fp16 single-pass, 2-mtile warps, double-buffered A) ----
#define OB 0                 // B image: 240 n * 304B = 72960
#define OA0 72960            // A buf0: 8 mtile * 9 ks * 512B = 36864
#define OA1 109824           // A buf1
#define OBIAS 146688         // 240 floats
#define OWL 147648           // 120 floats
#define SMEMT 148160
#define ABUF 36864
// MLP1
#define KCH 40
#define NCHUNK 250

__device__ u16   g_Bpack[2 * 240 * 152];   // [rank][n][152] fp16 weights, frag-permuted
__device__ float g_biasT[2 * 240];         // [rank][n] bias per gate col
__device__ float g_W2t[10000 * 256];
__device__ float g_spart[4 * 6400];        // [rank*2+nh][row]
__device__ float g_foo[Bz * Sz * Sz];
__device__ float g_part[NCHUNK * Bz * 256];
__device__ float g_part2[10 * Bz * 256];
__device__ float g_z1[Bz * 256];

__device__ __forceinline__ float tanh_a(float x){
    float y; asm("tanh.approx.f32 %0, %1;" : "=f"(y) : "f"(x)); return y;
}
__device__ __forceinline__ u16 h2u(float v){
    __half hh = __float2half_rn(v);
    return *reinterpret_cast<u16*>(&hh);
}
__device__ __forceinline__ u32 smaddr(const void* p){
    u32 a; asm("{ .reg .u64 t; cvta.to.shared.u64 t, %1; cvt.u32.u64 %0, t; }":"=r"(a):"l"(p)); return a;
}
__device__ __forceinline__ u32 mapa_peer(u32 la, u32 pr){
    u32 r; asm("mapa.shared::cluster.u32 %0, %1, %2;":"=r"(r):"r"(la),"r"(pr)); return r;
}
#define CARRIVE() asm volatile("barrier.cluster.arrive.aligned;":::"memory")
#define CWAIT()   asm volatile("barrier.cluster.wait.aligned;":::"memory")
#define MMAOP(d, a, b) asm volatile( \
    "mma.sync.aligned.m16n8k16.row.col.f32.f16.f16.f32 {%0,%1,%2,%3},{%4,%5,%6,%7},{%8,%9},{%0,%1,%2,%3};" \
    : "+f"((d)[0]), "+f"((d)[1]), "+f"((d)[2]), "+f"((d)[3]) \
    : "r"((a).x),"r"((a).y),"r"((a).z),"r"((a).w), "r"((b).x),"r"((b).y))

// ---------------- prep: B pack + bias ----------------
__global__ void prep_kernel(const float* __restrict__ Wih, const float* __restrict__ Whh,
                            const float* __restrict__ bih, const float* __restrict__ bhh) {
    int idx = blockIdx.x * blockDim.x + threadIdx.x, stride = gridDim.x * blockDim.x;
    for (int i = idx; i < 2 * 240 * 144; i += stride) {
        int k = i % 144, n = (i / 144) % 240, rank = i / (144 * 240);
        int g = n & 3, c = n >> 2;
        int j = g * 120 + rank * 60 + c;
        float v = 0.f;
        if (k < 16) v = Wih[j * 16 + k];
        else if (k < 136) v = Whh[j * 120 + (k - 16)];
        int pos = (k >> 4) * 16 + (((k & 15) & 7) >> 1) * 4 + (((k & 15) >> 3) & 1) * 2 + (k & 1);
        g_Bpack[((size_t)rank * 240 + n) * 152 + pos] = h2u(v);
    }
    for (int i = idx; i < 2 * 240; i += stride) {
        int n = i % 240, rank = i / 240;
        int j = (n & 3) * 120 + rank * 60 + (n >> 2);
        g_biasT[i] = bih[j] + bhh[j];
    }
}

// ---------------- W2 transpose, smem-tiled ----------------
__global__ void w2t_kernel(const float* __restrict__ W2) {
    __shared__ float tile[32][33];
    int k0 = blockIdx.x * 32, o0 = blockIdx.y * 32;
    int tx = threadIdx.x, ty = threadIdx.y;
    int k = k0 + tx, o = o0 + ty;
    if (k < 10000) tile[ty][tx] = W2[(size_t)o * 10000 + k];
    __syncthreads();
    int kk = k0 + ty, oo = o0 + tx;
    if (kk < 10000) g_W2t[(size_t)kk * 256 + oo] = tile[tx][ty];
}

// ---------------- warp-MMA LSTM ----------------
__device__ __forceinline__ void write_x(char* sm, u32 abase, int tid, float4 v0, float4 v1) {
    int lr = tid >> 1;
    float xv[8] = {v0.x, v0.y, v0.z, v0.w, v1.x, v1.y, v1.z, v1.w};
    u32 base = abase + (u32)((lr >> 4) * 9) * 512;
    #pragma unroll
    for (int j = 0; j < 4; j++) {
        int k = (tid & 1) * 8 + 2 * j;
        u32 off = base + (u32)(((lr & 7) * 4 + ((k & 7) >> 1)) * 16 + (((k >> 3) & 1) * 2 + ((lr >> 3) & 1)) * 4);
        *(u32*)(sm + off) = (u32)h2u(xv[2*j]) | ((u32)h2u(xv[2*j+1]) << 16);
    }
}

__global__ void __launch_bounds__(256, 1) __cluster_dims__(2, 1, 1)
lstm_mma(const float* __restrict__ x, const float* __restrict__ w_lin) {
    extern __shared__ char sm[];
    const int tid = threadIdx.x, w = tid >> 5, lane = tid & 31;
    const int q = lane & 3, rq = lane >> 2;
    const int wm = w & 3;         // mtile pair {wm, wm+4}
    const int nh = w >> 2;        // nf half (0..1), 15 nf each
    const u32 r = (u32)(blockIdx.x & 1);
    const int pair = blockIdx.x >> 1;
    const bool even = !(q & 1);
    const int lr = tid >> 1;
    const int xrow = pair * 128 + lr;
    const int xb = xrow / Sz, xs = xrow - xb * Sz;
    const float* xrowp = x + ((size_t)xb * Tz * Sz + xs) * 16 + (tid & 1) * 8;

    // init: B copy, A zero (both bufs), bias, w_lin
    {
        const int4* src = (const int4*)(g_Bpack + (size_t)r * (240 * 152));
        int4* dst = (int4*)sm;
        for (int i = tid; i < 72960 / 16; i += 256) dst[i] = src[i];
        int4 z = {0, 0, 0, 0};
        for (int i = tid; i < (2 * ABUF) / 16; i += 256) ((int4*)(sm + OA0))[i] = z;
        if (tid < 240) ((float*)(sm + OBIAS))[tid] = g_biasT[r * 240 + tid];
        if (tid < 120) ((float*)(sm + OWL))[tid] = w_lin[tid];
    }
    __syncthreads();
    {
        float4 v0 = *(const float4*)(xrowp);
        float4 v1 = *(const float4*)(xrowp + 4);
        write_x(sm, OA0, tid, v0, v1);
    }
    __syncthreads();
    CARRIVE(); CWAIT();

    const u32 remBase = mapa_peer(smaddr(sm), 1u ^ r);
    const float* wl = (const float*)(sm + OWL);
    const float* bias = (const float*)(sm + OBIAS);
    const char* Bp = sm + rq * 304 + q * 8;

    float cst[2][15], sacc0 = 0.f, sacc1 = 0.f;
    #pragma unroll
    for (int m = 0; m < 2; m++)
        #pragma unroll
        for (int i = 0; i < 15; i++) cst[m][i] = 0.f;

    for (int t = 0; t < Tz; ++t) {
        const bool last = (t == Tz - 1);
        const u32 cur = (t & 1) ? OA1 : OA0;
        const u32 nxt = (t & 1) ? OA0 : OA1;
        // prefetch x(t+1)
        float4 xv0, xv1;
        if (!last) {
            xv0 = *(const float4*)(xrowp + (size_t)(t + 1) * Sz * 16);
            xv1 = *(const float4*)(xrowp + (size_t)(t + 1) * Sz * 16 + 4);
        }
        // snapshot both mtiles of A
        uint4 ah0[9], ah1[9];
        {
            const char* a0 = sm + cur + wm * 4608 + lane * 16;
            const char* a1 = a0 + 4 * 4608;
            #pragma unroll
            for (int ks = 0; ks < 9; ks++) {
                ah0[ks] = *(const uint4*)(a0 + ks * 512);
                ah1[ks] = *(const uint4*)(a1 + ks * 512);
            }
        }

        #pragma unroll
        for (int nf = 0; nf < 15; nf++) {
            const int nfg = nh * 15 + nf;
            const char* Bn = Bp + nfg * 2432;
            float a0[4] = {0.f, 0.f, 0.f, 0.f};
            float a1[4] = {0.f, 0.f, 0.f, 0.f};
            #pragma unroll
            for (int ks = 0; ks < 9; ks++) {
                uint2 bh = *(const uint2*)(Bn + ks * 32);
                MMAOP(a0, ah0[ks], bh);
                MMAOP(a1, ah1[ks], bh);
            }
            float2 bv = *(const float2*)(bias + nfg * 8 + 2 * q);
            const int cidx = nfg * 2 + (q >> 1);
            const int k = 16 + (int)r * 60 + cidx;
            #pragma unroll
            for (int m = 0; m < 2; m++) {
                float* aa = m ? a1 : a0;
                float d0 = aa[0] + bv.x;
                float d1 = aa[1] + bv.y;
                float d2 = aa[2] + bv.x;
                float d3 = aa[3] + bv.y;
                float s0 = __shfl_xor_sync(~0u, even ? d2 : d0, 1);
                float s1 = __shfl_xor_sync(~0u, even ? d3 : d1, 1);
                float gi = even ? d0 : s0;
                float gf = even ? d1 : s1;
                float gg = even ? s0 : d2;
                float go = even ? s1 : d3;
                float si = fmaf(tanh_a(0.5f * gi), 0.5f, 0.5f);
                float sf = fmaf(tanh_a(0.5f * gf), 0.5f, 0.5f);
                float sg = tanh_a(gg);
                float so = fmaf(tanh_a(0.5f * go), 0.5f, 0.5f);
                float cc = fmaf(sf, cst[m][nf], si * sg);
                cst[m][nf] = cc;
                float h = so * tanh_a(cc);
                if (last) {
                    if (m) sacc1 = fmaf(h, wl[(int)r * 60 + cidx], sacc1);
                    else   sacc0 = fmaf(h, wl[(int)r * 60 + cidx], sacc0);
                } else {
                    const int mt = wm + 4 * m;
                    u32 off = nxt + (u32)((mt * 9 + (k >> 4)) * 512) +
                              (u32)((rq * 4 + ((k & 7) >> 1)) * 16 +
                                    (((k >> 3) & 1) * 2 + (q & 1)) * 4 + (k & 1) * 2);
                    u16 hh = h2u(h);
                    *(u16*)(sm + off) = hh;
                    asm volatile("st.shared::cluster.u16 [%0], %1;" :: "r"(remBase + off), "h"(hh) : "memory");
                }
            }
        }
        if (!last) write_x(sm, nxt, tid, xv0, xv1);
        CARRIVE();   // all writes to nxt issued
        CWAIT();     // visible cluster-wide before next snapshot
    }

    sacc0 += __shfl_xor_sync(~0u, sacc0, 2);
    sacc1 += __shfl_xor_sync(~0u, sacc1, 2);
    if (q < 2) {
        int slab = ((int)r * 2 + nh) * 6400;
        int row0 = pair * 128 + wm * 16 + rq + (q & 1) * 8;
        g_spart[slab + row0] = sacc0;
        g_spart[slab + row0 + 64] = sacc1;
    }
}

// ---------------- NeuralSort + softmax ----------------
__global__ void sort_kernel(const float* __restrict__ b_lin) {
    __shared__ float s_sm[Sz], rs_sm[Sz];
    int b = blockIdx.x, tid = threadIdx.x;
    if (tid < Sz) {
        int row = b * Sz + tid;
        s_sm[tid] = g_spart[row] + g_spart[6400 + row] + g_spart[2 * 6400 + row]
                  + g_spart[3 * 6400 + row] + b_lin[0];
    }
    __syncthreads();
    if (tid < Sz) {
        float si = s_sm[tid], sum = 0.f;
        for (int j = 0; j < Sz; j++) sum += fabsf(si - s_sm[j]);
        rs_sm[tid] = sum;
    }
    __syncthreads();
    int warp = tid >> 5, lane = tid & 31;
    for (int i = warp; i < Sz; i += 4) {
        float scal = (float)(Sz - 1 - 2 * i);
        float v[4], e[4], mx = -INFINITY;
        #pragma unroll
        for (int c = 0; c < 4; c++) {
            int j = lane + 32 * c;
            v[c] = (j < Sz) ? (s_sm[j] * scal - rs_sm[j]) * 0.2f : -INFINITY;
            mx = fmaxf(mx, v[c]);
        }
        #pragma unroll
        for (int o = 16; o; o >>= 1) mx = fmaxf(mx, __shfl_xor_sync(~0u, mx, o));
        float sum = 0.f;
        #pragma unroll
        for (int c = 0; c < 4; c++) {
            int j = lane + 32 * c;
            e[c] = (j < Sz) ? __expf(v[c] - mx) : 0.f;
            sum += e[c];
        }
        #pragma unroll
        for (int o = 16; o; o >>= 1) sum += __shfl_xor_sync(~0u, sum, o);
        float inv = __fdividef(1.f, sum);
        #pragma unroll
        for (int c = 0; c < 4; c++) {
            int j = lane + 32 * c;
            if (j < Sz) g_foo[(size_t)b * (Sz * Sz) + i * Sz + j] = e[c] * inv;
        }
    }
}

// ---------------- MLP1 K-split GEMM ----------------
__global__ void __launch_bounds__(256) mlp1_kernel() {
    int c = blockIdx.x, tid = threadIdx.x;
    int k0 = c * KCH, kend = k0 + KCH;
    int bg = tid >> 5, og = tid & 31;
    float acc[8][8];
    #pragma unroll
    for (int i = 0; i < 8; i++)
        #pragma unroll
        for (int j = 0; j < 8; j++) acc[i][j] = 0.f;
    const float* fooB = g_foo + (size_t)(bg * 8) * 10000;
    for (int k = k0; k < kend; ++k) {
        float a[8];
        #pragma unroll
        for (int i = 0; i < 8; i++) a[i] = fooB[(size_t)i * 10000 + k];
        float4 w0 = *(const float4*)(g_W2t + (size_t)k * 256 + og * 8);
        float4 w1 = *(const float4*)(g_W2t + (size_t)k * 256 + og * 8 + 4);
        float wv[8] = {w0.x, w0.y, w0.z, w0.w, w1.x, w1.y, w1.z, w1.w};
        #pragma unroll
        for (int i = 0; i < 8; i++)
            #pragma unroll
            for (int j = 0; j < 8; j++) acc[i][j] = fmaf(a[i], wv[j], acc[i][j]);
    }
    #pragma unroll
    for (int i = 0; i < 8; i++)
        #pragma unroll
        for (int j = 0; j < 8; j++)
            g_part[((size_t)c * 64 + bg * 8 + i) * 256 + og * 8 + j] = acc[i][j];
}

// ---------------- two-stage reduce + relu ----------------
__global__ void reduce1_kernel() {
    int b = blockIdx.x, cg = blockIdx.y, o = threadIdx.x;
    float s = 0.f;
    #pragma unroll 5
    for (int c = cg * 25; c < cg * 25 + 25; ++c)
        s += g_part[((size_t)c * 64 + b) * 256 + o];
    g_part2[((size_t)cg * 64 + b) * 256 + o] = s;
}
__global__ void reduce2_kernel(const float* __restrict__ b2) {
    int b = blockIdx.x, o = threadIdx.x;
    float s = b2[o];
    #pragma unroll
    for (int g = 0; g < 10; ++g) s += g_part2[((size_t)g * 64 + b) * 256 + o];
    g_z1[b * 256 + o] = fmaxf(s, 0.f);
}

__global__ void mlp2_kernel(const float* __restrict__ W3, const float* __restrict__ b3,
                            float* __restrict__ out) {
    __shared__ float z1s[256], zs[Sz], s_mx, s_sum;
    int b = blockIdx.x, tid = threadIdx.x;
    z1s[tid] = g_z1[b * 256 + tid];
    z1s[tid + 128] = g_z1[b * 256 + tid + 128];
    __syncthreads();
    if (tid < Sz) {
        float a = b3[tid];
        const float* wr = W3 + tid * 256;
        #pragma unroll 4
        for (int k = 0; k < 256; k++) a = fmaf(z1s[k], wr[k], a);
        zs[tid] = a;
    }
    __syncthreads();
    if (tid == 0) {
        float mx = -INFINITY;
        for (int j = 0; j < Sz; j++) mx = fmaxf(mx, zs[j]);
        float sum = 0.f;
        for (int j = 0; j < Sz; j++) sum += __expf(zs[j] - mx);
        s_mx = mx; s_sum = sum;
    }
    __syncthreads();
    if (tid < Sz) out[b * Sz + tid] = __expf(zs[tid] - s_mx) * __fdividef(1.f, s_sum);
}

extern "C" void kernel_launch(void* const* d_in, const int* in_sizes, int n_in,
                              void* d_out, int out_size) {
    const float* x    = (const float*)d_in[0];
    const float* Wih  = (const float*)d_in[1];
    const float* Whh  = (const float*)d_in[2];
    const float* bih  = (const float*)d_in[3];
    const float* bhh  = (const float*)d_in[4];
    const float* wlin = (const float*)d_in[5];
    const float* blin = (const float*)d_in[6];
    const float* W2   = (const float*)d_in[7];
    const float* b2   = (const float*)d_in[8];
    const float* W3   = (const float*)d_in[9];
    const float* b3   = (const float*)d_in[10];
    float* out = (float*)d_out;
    (void)in_sizes; (void)n_in; (void)out_size;

    cudaFuncSetAttribute(lstm_mma, cudaFuncAttributeMaxDynamicSharedMemorySize, SMEMT);
    prep_kernel<<<256, 256>>>(Wih, Whh, bih, bhh);
    w2t_kernel<<<dim3(313, 8), dim3(32, 32)>>>(W2);
    lstm_mma<<<100, 256, SMEMT>>>(x, wlin);
    sort_kernel<<<Bz, 128>>>(blin);
    mlp1_kernel<<<NCHUNK, 256>>>();
    reduce1_kernel<<<dim3(Bz, 10), 256>>>();
    reduce2_kernel<<<Bz, 256>>>(b2);
    mlp2_kernel<<<Bz, 128>>>(W3, b3, out);
}

// round 12
// speedup vs baseline: 6.5692x; 1.1801x over previous
#include <cuda_runtime.h>
#include <cuda_fp16.h>
#include <math.h>

#define Bz 64
#define Tz 128
#define Sz 100
typedef unsigned int u32; typedef unsigned short u16;

// ---- LSTM mma config (fp16 single-pass, 64-row CTAs, all-local) ----
#define OB 0                 // B image: 480 n * 304B = 145920
#define OA0 145920           // A buf0: 4 mtile * 9 ks * 512B = 18432
#define OA1 164352           // A buf1
#define OBIAS 182784         // 480 floats
#define OWL 184704           // 120 floats
#define SMEMT 185216
#define ABUF 18432
// MLP1
#define KCH 40
#define NCHUNK 250

__device__ u16   g_Bpack[480 * 152];       // [n][152] fp16 weights, frag-permuted
__device__ float g_biasT[480];             // [n] bias per gate col
__device__ float g_W2t[10000 * 256];
__device__ float g_spart[4 * 6400];        // [nh][row]
__device__ float g_foo[Bz * Sz * Sz];
__device__ float g_part[NCHUNK * Bz * 256];
__device__ float g_part2[10 * Bz * 256];
__device__ float g_z1[Bz * 256];

__device__ __forceinline__ float tanh_a(float x){
    float y; asm("tanh.approx.f32 %0, %1;" : "=f"(y) : "f"(x)); return y;
}
__device__ __forceinline__ u16 h2u(float v){
    __half hh = __float2half_rn(v);
    return *reinterpret_cast<u16*>(&hh);
}
#define MMAOP(d, a, b) asm volatile( \
    "mma.sync.aligned.m16n8k16.row.col.f32.f16.f16.f32 {%0,%1,%2,%3},{%4,%5,%6,%7},{%8,%9},{%0,%1,%2,%3};" \
    : "+f"((d)[0]), "+f"((d)[1]), "+f"((d)[2]), "+f"((d)[3]) \
    : "r"((a).x),"r"((a).y),"r"((a).z),"r"((a).w), "r"((b).x),"r"((b).y))

// ---------------- prep: B pack + bias ----------------
__global__ void prep_kernel(const float* __restrict__ Wih, const float* __restrict__ Whh,
                            const float* __restrict__ bih, const float* __restrict__ bhh) {
    int idx = blockIdx.x * blockDim.x + threadIdx.x, stride = gridDim.x * blockDim.x;
    for (int i = idx; i < 480 * 144; i += stride) {
        int k = i % 144, n = i / 144;
        int g = n & 3, c = n >> 2;           // cell 0..119
        int j = g * 120 + c;
        float v = 0.f;
        if (k < 16) v = Wih[j * 16 + k];
        else if (k < 136) v = Whh[j * 120 + (k - 16)];
        int pos = (k >> 4) * 16 + (((k & 15) & 7) >> 1) * 4 + (((k & 15) >> 3) & 1) * 2 + (k & 1);
        g_Bpack[(size_t)n * 152 + pos] = h2u(v);
    }
    for (int i = idx; i < 480; i += stride) {
        int j = (i & 3) * 120 + (i >> 2);
        g_biasT[i] = bih[j] + bhh[j];
    }
}

// ---------------- W2 transpose, smem-tiled ----------------
__global__ void w2t_kernel(const float* __restrict__ W2) {
    __shared__ float tile[32][33];
    int k0 = blockIdx.x * 32, o0 = blockIdx.y * 32;
    int tx = threadIdx.x, ty = threadIdx.y;
    int k = k0 + tx, o = o0 + ty;
    if (k < 10000) tile[ty][tx] = W2[(size_t)o * 10000 + k];
    __syncthreads();
    int kk = k0 + ty, oo = o0 + tx;
    if (kk < 10000) g_W2t[(size_t)kk * 256 + oo] = tile[tx][ty];
}

// ---------------- warp-MMA LSTM (all-local, 64 rows/CTA) ----------------
__device__ __forceinline__ void write_x(char* sm, u32 abase, int tid, float4 v0, float4 v1) {
    int lr = tid >> 1;                       // row 0..63
    float xv[8] = {v0.x, v0.y, v0.z, v0.w, v1.x, v1.y, v1.z, v1.w};
    u32 base = abase + (u32)((lr >> 4) * 9) * 512;
    #pragma unroll
    for (int j = 0; j < 4; j++) {
        int k = (tid & 1) * 8 + 2 * j;
        u32 off = base + (u32)(((lr & 7) * 4 + ((k & 7) >> 1)) * 16 + (((k >> 3) & 1) * 2 + ((lr >> 3) & 1)) * 4);
        *(u32*)(sm + off) = (u32)h2u(xv[2*j]) | ((u32)h2u(xv[2*j+1]) << 16);
    }
}

__global__ void __launch_bounds__(256, 1)
lstm_mma(const float* __restrict__ x, const float* __restrict__ w_lin) {
    extern __shared__ char sm[];
    const int tid = threadIdx.x, w = tid >> 5, lane = tid & 31;
    const int q = lane & 3, rq = lane >> 2;
    const int wm = w & 1;         // mtile pair {wm, wm+2}
    const int nh = w >> 1;        // nf quarter (0..3), 15 nf each
    const bool even = !(q & 1);
    const int row0 = blockIdx.x * 64;
    const bool xact = tid < 128;  // 2 threads per row for x staging
    const int lr = tid >> 1;
    const int xrow = row0 + (xact ? lr : 0);
    const int xb = xrow / Sz, xs = xrow - xb * Sz;
    const float* xrowp = x + ((size_t)xb * Tz * Sz + xs) * 16 + (tid & 1) * 8;

    // init: B copy, A zero (both bufs), bias, w_lin
    {
        const int4* src = (const int4*)g_Bpack;
        int4* dst = (int4*)sm;
        for (int i = tid; i < 145920 / 16; i += 256) dst[i] = src[i];
        int4 z = {0, 0, 0, 0};
        for (int i = tid; i < (2 * ABUF) / 16; i += 256) ((int4*)(sm + OA0))[i] = z;
        if (tid < 240) {
            ((float*)(sm + OBIAS))[tid] = g_biasT[tid];
            ((float*)(sm + OBIAS))[tid + 240] = g_biasT[tid + 240];
        }
        if (tid < 120) ((float*)(sm + OWL))[tid] = w_lin[tid];
    }
    __syncthreads();
    if (xact) {
        float4 v0 = *(const float4*)(xrowp);
        float4 v1 = *(const float4*)(xrowp + 4);
        write_x(sm, OA0, tid, v0, v1);
    }
    __syncthreads();

    const float* wl = (const float*)(sm + OWL);
    const float* bias = (const float*)(sm + OBIAS);
    const char* Bp = sm + rq * 304 + q * 8;

    float cst[2][15], sacc0 = 0.f, sacc1 = 0.f;
    #pragma unroll
    for (int m = 0; m < 2; m++)
        #pragma unroll
        for (int i = 0; i < 15; i++) cst[m][i] = 0.f;

    for (int t = 0; t < Tz; ++t) {
        const bool last = (t == Tz - 1);
        const u32 cur = (t & 1) ? OA1 : OA0;
        const u32 nxt = (t & 1) ? OA0 : OA1;
        // prefetch x(t+1)
        float4 xv0, xv1;
        if (!last && xact) {
            xv0 = *(const float4*)(xrowp + (size_t)(t + 1) * Sz * 16);
            xv1 = *(const float4*)(xrowp + (size_t)(t + 1) * Sz * 16 + 4);
        }
        // snapshot both mtiles of A (reads cur; writes this step go to nxt)
        uint4 ah0[9], ah1[9];
        {
            const char* a0 = sm + cur + wm * 4608 + lane * 16;
            const char* a1 = a0 + 2 * 4608;
            #pragma unroll
            for (int ks = 0; ks < 9; ks++) {
                ah0[ks] = *(const uint4*)(a0 + ks * 512);
                ah1[ks] = *(const uint4*)(a1 + ks * 512);
            }
        }

        #pragma unroll
        for (int nf = 0; nf < 15; nf++) {
            const int nfg = nh * 15 + nf;
            const char* Bn = Bp + nfg * 2432;
            float a0[4] = {0.f, 0.f, 0.f, 0.f};
            float a1[4] = {0.f, 0.f, 0.f, 0.f};
            #pragma unroll
            for (int ks = 0; ks < 9; ks++) {
                uint2 bh = *(const uint2*)(Bn + ks * 32);
                MMAOP(a0, ah0[ks], bh);
                MMAOP(a1, ah1[ks], bh);
            }
            float2 bv = *(const float2*)(bias + nfg * 8 + 2 * q);
            const int cidx = nfg * 2 + (q >> 1);   // cell 0..119
            const int k = 16 + cidx;
            #pragma unroll
            for (int m = 0; m < 2; m++) {
                float* aa = m ? a1 : a0;
                float d0 = aa[0] + bv.x;
                float d1 = aa[1] + bv.y;
                float d2 = aa[2] + bv.x;
                float d3 = aa[3] + bv.y;
                float s0 = __shfl_xor_sync(~0u, even ? d2 : d0, 1);
                float s1 = __shfl_xor_sync(~0u, even ? d3 : d1, 1);
                float gi = even ? d0 : s0;
                float gf = even ? d1 : s1;
                float gg = even ? s0 : d2;
                float go = even ? s1 : d3;
                float si = fmaf(tanh_a(0.5f * gi), 0.5f, 0.5f);
                float sf = fmaf(tanh_a(0.5f * gf), 0.5f, 0.5f);
                float sg = tanh_a(gg);
                float so = fmaf(tanh_a(0.5f * go), 0.5f, 0.5f);
                float cc = fmaf(sf, cst[m][nf], si * sg);
                cst[m][nf] = cc;
                float h = so * tanh_a(cc);
                if (last) {
                    if (m) sacc1 = fmaf(h, wl[cidx], sacc1);
                    else   sacc0 = fmaf(h, wl[cidx], sacc0);
                } else {
                    const int mt = wm + 2 * m;
                    u32 off = nxt + (u32)((mt * 9 + (k >> 4)) * 512) +
                              (u32)((rq * 4 + ((k & 7) >> 1)) * 16 +
                                    (((k >> 3) & 1) * 2 + (q & 1)) * 4 + (k & 1) * 2);
                    *(u16*)(sm + off) = h2u(h);
                }
            }
        }
        if (!last && xact) write_x(sm, nxt, tid, xv0, xv1);
        __syncthreads();   // all reads of cur + writes of nxt complete
    }

    sacc0 += __shfl_xor_sync(~0u, sacc0, 2);
    sacc1 += __shfl_xor_sync(~0u, sacc1, 2);
    if (q < 2) {
        int slab = nh * 6400;
        int rbase = row0 + rq + (q & 1) * 8;
        g_spart[slab + rbase + (wm + 0) * 16] = sacc0;
        g_spart[slab + rbase + (wm + 2) * 16] = sacc1;
    }
}

// ---------------- NeuralSort + softmax ----------------
__global__ void sort_kernel(const float* __restrict__ b_lin) {
    __shared__ float s_sm[Sz], rs_sm[Sz];
    int b = blockIdx.x, tid = threadIdx.x;
    if (tid < Sz) {
        int row = b * Sz + tid;
        s_sm[tid] = g_spart[row] + g_spart[6400 + row] + g_spart[2 * 6400 + row]
                  + g_spart[3 * 6400 + row] + b_lin[0];
    }
    __syncthreads();
    if (tid < Sz) {
        float si = s_sm[tid], sum = 0.f;
        for (int j = 0; j < Sz; j++) sum += fabsf(si - s_sm[j]);
        rs_sm[tid] = sum;
    }
    __syncthreads();
    int warp = tid >> 5, lane = tid & 31;
    for (int i = warp; i < Sz; i += 4) {
        float scal = (float)(Sz - 1 - 2 * i);
        float v[4], e[4], mx = -INFINITY;
        #pragma unroll
        for (int c = 0; c < 4; c++) {
            int j = lane + 32 * c;
            v[c] = (j < Sz) ? (s_sm[j] * scal - rs_sm[j]) * 0.2f : -INFINITY;
            mx = fmaxf(mx, v[c]);
        }
        #pragma unroll
        for (int o = 16; o; o >>= 1) mx = fmaxf(mx, __shfl_xor_sync(~0u, mx, o));
        float sum = 0.f;
        #pragma unroll
        for (int c = 0; c < 4; c++) {
            int j = lane + 32 * c;
            e[c] = (j < Sz) ? __expf(v[c] - mx) : 0.f;
            sum += e[c];
        }
        #pragma unroll
        for (int o = 16; o; o >>= 1) sum += __shfl_xor_sync(~0u, sum, o);
        float inv = __fdividef(1.f, sum);
        #pragma unroll
        for (int c = 0; c < 4; c++) {
            int j = lane + 32 * c;
            if (j < Sz) g_foo[(size_t)b * (Sz * Sz) + i * Sz + j] = e[c] * inv;
        }
    }
}

// ---------------- MLP1 K-split GEMM ----------------
__global__ void __launch_bounds__(256) mlp1_kernel() {
    int c = blockIdx.x, tid = threadIdx.x;
    int k0 = c * KCH, kend = k0 + KCH;
    int bg = tid >> 5, og = tid & 31;
    float acc[8][8];
    #pragma unroll
    for (int i = 0; i < 8; i++)
        #pragma unroll
        for (int j = 0; j < 8; j++) acc[i][j] = 0.f;
    const float* fooB = g_foo + (size_t)(bg * 8) * 10000;
    for (int k = k0; k < kend; ++k) {
        float a[8];
        #pragma unroll
        for (int i = 0; i < 8; i++) a[i] = fooB[(size_t)i * 10000 + k];
        float4 w0 = *(const float4*)(g_W2t + (size_t)k * 256 + og * 8);
        float4 w1 = *(const float4*)(g_W2t + (size_t)k * 256 + og * 8 + 4);
        float wv[8] = {w0.x, w0.y, w0.z, w0.w, w1.x, w1.y, w1.z, w1.w};
        #pragma unroll
        for (int i = 0; i < 8; i++)
            #pragma unroll
            for (int j = 0; j < 8; j++) acc[i][j] = fmaf(a[i], wv[j], acc[i][j]);
    }
    #pragma unroll
    for (int i = 0; i < 8; i++)
        #pragma unroll
        for (int j = 0; j < 8; j++)
            g_part[((size_t)c * 64 + bg * 8 + i) * 256 + og * 8 + j] = acc[i][j];
}

// ---------------- two-stage reduce + relu ----------------
__global__ void reduce1_kernel() {
    int b = blockIdx.x, cg = blockIdx.y, o = threadIdx.x;
    float s = 0.f;
    #pragma unroll 5
    for (int c = cg * 25; c < cg * 25 + 25; ++c)
        s += g_part[((size_t)c * 64 + b) * 256 + o];
    g_part2[((size_t)cg * 64 + b) * 256 + o] = s;
}
__global__ void reduce2_kernel(const float* __restrict__ b2) {
    int b = blockIdx.x, o = threadIdx.x;
    float s = b2[o];
    #pragma unroll
    for (int g = 0; g < 10; ++g) s += g_part2[((size_t)g * 64 + b) * 256 + o];
    g_z1[b * 256 + o] = fmaxf(s, 0.f);
}

__global__ void mlp2_kernel(const float* __restrict__ W3, const float* __restrict__ b3,
                            float* __restrict__ out) {
    __shared__ float z1s[256], zs[Sz], s_mx, s_sum;
    int b = blockIdx.x, tid = threadIdx.x;
    z1s[tid] = g_z1[b * 256 + tid];
    z1s[tid + 128] = g_z1[b * 256 + tid + 128];
    __syncthreads();
    if (tid < Sz) {
        float a = b3[tid];
        const float* wr = W3 + tid * 256;
        #pragma unroll 4
        for (int k = 0; k < 256; k++) a = fmaf(z1s[k], wr[k], a);
        zs[tid] = a;
    }
    __syncthreads();
    if (tid == 0) {
        float mx = -INFINITY;
        for (int j = 0; j < Sz; j++) mx = fmaxf(mx, zs[j]);
        float sum = 0.f;
        for (int j = 0; j < Sz; j++) sum += __expf(zs[j] - mx);
        s_mx = mx; s_sum = sum;
    }
    __syncthreads();
    if (tid < Sz) out[b * Sz + tid] = __expf(zs[tid] - s_mx) * __fdividef(1.f, s_sum);
}

extern "C" void kernel_launch(void* const* d_in, const int* in_sizes, int n_in,
                              void* d_out, int out_size) {
    const float* x    = (const float*)d_in[0];
    const float* Wih  = (const float*)d_in[1];
    const float* Whh  = (const float*)d_in[2];
    const float* bih  = (const float*)d_in[3];
    const float* bhh  = (const float*)d_in[4];
    const float* wlin = (const float*)d_in[5];
    const float* blin = (const float*)d_in[6];
    const float* W2   = (const float*)d_in[7];
    const float* b2   = (const float*)d_in[8];
    const float* W3   = (const float*)d_in[9];
    const float* b3   = (const float*)d_in[10];
    float* out = (float*)d_out;
    (void)in_sizes; (void)n_in; (void)out_size;

    cudaFuncSetAttribute(lstm_mma, cudaFuncAttributeMaxDynamicSharedMemorySize, SMEMT);
    prep_kernel<<<256, 256>>>(Wih, Whh, bih, bhh);
    w2t_kernel<<<dim3(313, 8), dim3(32, 32)>>>(W2);
    lstm_mma<<<100, 256, SMEMT>>>(x, wlin);
    sort_kernel<<<Bz, 128>>>(blin);
    mlp1_kernel<<<NCHUNK, 256>>>();
    reduce1_kernel<<<dim3(Bz, 10), 256>>>();
    reduce2_kernel<<<Bz, 256>>>(b2);
    mlp2_kernel<<<Bz, 128>>>(W3, b3, out);
}